// round 4
// baseline (speedup 1.0000x reference)
#include <cuda_runtime.h>
#include <math_constants.h>

#define NSAMPLE 16
#define NPTS    8192
#define BATCH   2
#define CH      64
#define OUTCH   128
#define SEG     4
#define SEGSZ   (NPTS / SEG)      // 2048

typedef unsigned long long ull;

// ---- f32x2 packed helpers (Blackwell) ----
__device__ __forceinline__ ull pk2(float a, float b) {
    ull r; asm("mov.b64 %0,{%1,%2};" : "=l"(r) : "f"(a), "f"(b)); return r;
}
__device__ __forceinline__ void upk2(float& a, float& b, ull r) {
    asm("mov.b64 {%0,%1}, %2;" : "=f"(a), "=f"(b) : "l"(r));
}
__device__ __forceinline__ ull fma2_(ull a, ull b, ull c) {
    ull d; asm("fma.rn.f32x2 %0,%1,%2,%3;" : "=l"(d) : "l"(a), "l"(b), "l"(c)); return d;
}
__device__ __forceinline__ ull add2_(ull a, ull b) {
    ull d; asm("add.rn.f32x2 %0,%1,%2;" : "=l"(d) : "l"(a), "l"(b)); return d;
}
__device__ __forceinline__ ull mul2_(ull a, ull b) {
    ull d; asm("mul.rn.f32x2 %0,%1,%2;" : "=l"(d) : "l"(a), "l"(b)); return d;
}
__device__ __forceinline__ float leaky(float x) { return x >= 0.0f ? x : 0.1f * x; }

// scratch
__device__ float4 g_pts4[2 * BATCH * NPTS];                 // [cloud][b][n]
__device__ float2 g_part[2 * BATCH * NPTS * SEG * NSAMPLE]; // per-segment top16 (d, idx)
__device__ int    g_knn[2 * BATCH * NPTS * NSAMPLE];
__device__ float  g_ms[2 * BATCH * NPTS * CH];

// ---------------------------------------------------------------------------
__global__ void pack_kernel(const float* __restrict__ pc1,
                            const float* __restrict__ pc2) {
    int i = blockIdx.x * blockDim.x + threadIdx.x;
    if (i >= 2 * BATCH * NPTS) return;
    const float* src = (i < BATCH * NPTS) ? pc1 : pc2;
    int r = (i < BATCH * NPTS) ? i : (i - BATCH * NPTS);
    float x = src[r * 3 + 0], y = src[r * 3 + 1], z = src[r * 3 + 2];
    g_pts4[i] = make_float4(x, y, z, x * x + y * y + z * z);
}

// ---------------------------------------------------------------------------
// predicated top-16 set update (registers only)
// ---------------------------------------------------------------------------
__device__ __forceinline__ void upd16(float d, int idx,
                                      float (&bd)[NSAMPLE], int (&bi)[NSAMPLE],
                                      float& wd, int& maxp) {
#pragma unroll
    for (int k = 0; k < NSAMPLE; k++) {
        bool s = (k == maxp);
        bd[k] = s ? d   : bd[k];
        bi[k] = s ? idx : bi[k];
    }
    float v8[8]; int i8[8];
#pragma unroll
    for (int k = 0; k < 8; k++) {
        bool s = bd[2*k+1] > bd[2*k];
        v8[k] = s ? bd[2*k+1] : bd[2*k];
        i8[k] = s ? 2*k+1     : 2*k;
    }
    float v4[4]; int i4[4];
#pragma unroll
    for (int k = 0; k < 4; k++) {
        bool s = v8[2*k+1] > v8[2*k];
        v4[k] = s ? v8[2*k+1] : v8[2*k];
        i4[k] = s ? i8[2*k+1] : i8[2*k];
    }
    float v2[2]; int i2[2];
#pragma unroll
    for (int k = 0; k < 2; k++) {
        bool s = v4[2*k+1] > v4[2*k];
        v2[k] = s ? v4[2*k+1] : v4[2*k];
        i2[k] = s ? i4[2*k+1] : i4[2*k];
    }
    bool s = v2[1] > v2[0];
    wd   = s ? v2[1] : v2[0];
    maxp = s ? i2[1] : i2[0];
}

// ---------------------------------------------------------------------------
// KNN pass 1: per (query, segment) top-16 over 2048 candidates.
// SoA smem, f32x2 packed distances (4 candidates / iter).
// ---------------------------------------------------------------------------
__global__ void __launch_bounds__(128) knn_part() {
    __shared__ float sx[SEGSZ], sy[SEGSZ], sz[SEGSZ], sw[SEGSZ];

    const int dirb = blockIdx.y;               // dir*2 + b
    const int dir  = dirb >> 1;
    const int b    = dirb & 1;
    const int seg  = blockIdx.z;
    const int n    = blockIdx.x * 128 + threadIdx.x;

    const float4* Qb = g_pts4 + ((size_t)dir * BATCH + b) * NPTS;
    const float4* Cb = g_pts4 + ((size_t)(1 - dir) * BATCH + b) * NPTS + seg * SEGSZ;

    for (int i = threadIdx.x; i < SEGSZ; i += 128) {
        float4 c = Cb[i];
        sx[i] = c.x; sy[i] = c.y; sz[i] = c.z; sw[i] = c.w;
    }
    __syncthreads();

    const float4 q = Qb[n];
    const ull qx2 = pk2(q.x, q.x);
    const ull qy2 = pk2(q.y, q.y);
    const ull qz2 = pk2(q.z, q.z);
    const ull sq2 = pk2(q.w, q.w);
    const ull m2  = pk2(-2.0f, -2.0f);

    float bd[NSAMPLE]; int bi[NSAMPLE];
#pragma unroll
    for (int k = 0; k < NSAMPLE; k++) { bd[k] = CUDART_INF_F; bi[k] = 0; }
    float wd = CUDART_INF_F; int maxp = 0;
    const int base = seg * SEGSZ;

#pragma unroll 2
    for (int j = 0; j < SEGSZ; j += 4) {
        ulonglong2 X = *reinterpret_cast<const ulonglong2*>(&sx[j]);
        ulonglong2 Y = *reinterpret_cast<const ulonglong2*>(&sy[j]);
        ulonglong2 Z = *reinterpret_cast<const ulonglong2*>(&sz[j]);
        ulonglong2 W = *reinterpret_cast<const ulonglong2*>(&sw[j]);
        ull t01 = fma2_(qx2, X.x, fma2_(qy2, Y.x, mul2_(qz2, Z.x)));
        ull t23 = fma2_(qx2, X.y, fma2_(qy2, Y.y, mul2_(qz2, Z.y)));
        ull d01 = fma2_(m2, t01, add2_(sq2, W.x));
        ull d23 = fma2_(m2, t23, add2_(sq2, W.y));
        float d0, d1, d2, d3;
        upk2(d0, d1, d01);
        upk2(d2, d3, d23);
        if (d0 < wd) upd16(d0, base + j + 0, bd, bi, wd, maxp);
        if (d1 < wd) upd16(d1, base + j + 1, bd, bi, wd, maxp);
        if (d2 < wd) upd16(d2, base + j + 2, bd, bi, wd, maxp);
        if (d3 < wd) upd16(d3, base + j + 3, bd, bi, wd, maxp);
    }

    float2* outp = g_part + (((size_t)dirb * NPTS + n) * SEG + seg) * NSAMPLE;
#pragma unroll
    for (int k = 0; k < NSAMPLE; k++)
        outp[k] = make_float2(bd[k], __int_as_float(bi[k]));
}

// ---------------------------------------------------------------------------
// KNN pass 2: warp per query merges 4x16 -> exact top-16 (lex (d, idx)).
// ---------------------------------------------------------------------------
__global__ void __launch_bounds__(256) knn_merge() {
    const int gtid = blockIdx.x * 256 + threadIdx.x;
    const int q    = gtid >> 5;           // query id 0..32767
    const int lane = gtid & 31;

    const float2* pp = g_part + (size_t)q * (SEG * NSAMPLE);
    float2 e0 = pp[lane];
    float2 e1 = pp[lane + 32];
    float d0 = e0.x; int i0 = __float_as_int(e0.y);
    float d1 = e1.x; int i1 = __float_as_int(e1.y);

    int* outp = g_knn + (size_t)q * NSAMPLE;

#pragma unroll
    for (int k = 0; k < NSAMPLE; k++) {
        bool t = (d1 < d0) || (d1 == d0 && i1 < i0);
        float bdv = t ? d1 : d0;
        int   biv = t ? i1 : i0;
#pragma unroll
        for (int off = 16; off > 0; off >>= 1) {
            float od = __shfl_xor_sync(0xFFFFFFFFu, bdv, off);
            int   oi = __shfl_xor_sync(0xFFFFFFFFu, biv, off);
            if (od < bdv || (od == bdv && oi < biv)) { bdv = od; biv = oi; }
        }
        if (lane == 0) outp[k] = biv;
        if (d0 == bdv && i0 == biv)      d0 = CUDART_INF_F;
        else if (d1 == bdv && i1 == biv) d1 = CUDART_INF_F;
    }
}

// ---------------------------------------------------------------------------
// feat: 128 threads = 8 points x 16 threads; per thread k8 x o8 tile with
// f32x2 o-pair accumulators. Padded smem strides for conflict-free access.
// ---------------------------------------------------------------------------
#define WSTR 68                         // weight row stride (floats)
#define HROWS 68                        // hs k-row stride
#define HPNT  1128                      // hs per-point stride (mod 32 == 8)

__device__ __forceinline__ int hoff(int p, int k) {
    return p * HPNT + k * HROWS + ((k >> 3) << 4);
}

__global__ void __launch_bounds__(128) feat_kernel(
        const float* __restrict__ feat1,
        const float* __restrict__ feat2,
        const float* __restrict__ pos_w,
        const float* __restrict__ pos_b,
        const float* __restrict__ w0,
        const float* __restrict__ b0,
        const float* __restrict__ w1,
        const float* __restrict__ b1) {
    extern __shared__ float sm[];
    float* w0T   = sm;                         // 64*68 = 4352
    float* w1T   = w0T + 64 * WSTR;            // 4352
    float* hs    = w1T + 64 * WSTR;            // 8*1128 = 9024
    float* pm    = hs + 8 * HPNT;              // 8*128 = 1024
    float* posws = pm + 1024;                  // 192
    float* posbs = posws + 192;                // 64
    float* b0s   = posbs + 64;                 // 64
    float* b1s   = b0s + 64;                   // 64

    const int dir = blockIdx.z;
    const int b   = blockIdx.y;
    const int tid = threadIdx.x;
    const int dirb = dir * BATCH + b;

    // cooperative weight transpose: coalesced float4 read, 2-way-conflict STS
    for (int it = 0; it < 8; it++) {
        int f = tid + it * 128;                // float4 index
        float4 a = reinterpret_cast<const float4*>(w0)[f];
        float4 c = reinterpret_cast<const float4*>(w1)[f];
        int o = f >> 4, c0 = (f & 15) * 4;
        w0T[(c0 + 0) * WSTR + o] = a.x;
        w0T[(c0 + 1) * WSTR + o] = a.y;
        w0T[(c0 + 2) * WSTR + o] = a.z;
        w0T[(c0 + 3) * WSTR + o] = a.w;
        w1T[(c0 + 0) * WSTR + o] = c.x;
        w1T[(c0 + 1) * WSTR + o] = c.y;
        w1T[(c0 + 2) * WSTR + o] = c.z;
        w1T[(c0 + 3) * WSTR + o] = c.w;
    }
    if (tid < 64) {
        posbs[tid] = pos_b[tid];
        b0s[tid]   = b0[tid];
        b1s[tid]   = b1[tid];
    }
    // FIX (R3 bug): 128-thread block must stride to cover all 192 pos weights
    for (int i = tid; i < 192; i += 128) posws[i] = pos_w[i];
    __syncthreads();

    const float* F1 = dir ? feat2 : feat1;
    const float* F2 = dir ? feat1 : feat2;
    const float4* QC = g_pts4 + ((size_t)dir * BATCH + b) * NPTS;
    const float4* NC = g_pts4 + ((size_t)(1 - dir) * BATCH + b) * NPTS;

    // ---- stage 1: gather + pos feat + leaky -> hs ----
    {
        const int c  = tid & 63;
        const int rh = tid >> 6;
        const float pwx = posws[c * 3 + 0];
        const float pwy = posws[c * 3 + 1];
        const float pwz = posws[c * 3 + 2];
        const float pb  = posbs[c];
        for (int it = 0; it < 64; it++) {
            int row = it * 2 + rh;
            int p = row >> 4, k = row & 15;
            int n = blockIdx.x * 8 + p;
            int id = g_knn[((size_t)dirb * NPTS + n) * NSAMPLE + k];
            float4 cc = NC[id];
            float4 qq = QC[n];
            float g   = F2[((size_t)b * NPTS + id) * CH + c];
            float p1o = F1[((size_t)b * NPTS + n) * CH + c];
            float h = g + p1o +
                fmaf(pwx, cc.x - qq.x, fmaf(pwy, cc.y - qq.y,
                fmaf(pwz, cc.z - qq.z, pb)));
            hs[hoff(p, k) + c] = leaky(h);
        }
    }
    __syncthreads();

    const int tt = tid & 15;
    const int p  = tid >> 4;
    const int o0 = (tt & 7) * 8;
    const int k0 = (tt >> 3) * 8;
    float* hp2 = hs + hoff(p, k0);   // rows k0..k0+7 contiguous at stride HROWS

    ull acc[8][4];

    // =============== layer 1 ===============
    {
        ulonglong2 bA = *reinterpret_cast<const ulonglong2*>(b0s + o0);
        ulonglong2 bB = *reinterpret_cast<const ulonglong2*>(b0s + o0 + 4);
#pragma unroll
        for (int ki = 0; ki < 8; ki++) {
            acc[ki][0] = bA.x; acc[ki][1] = bA.y;
            acc[ki][2] = bB.x; acc[ki][3] = bB.y;
        }
#pragma unroll 1
        for (int c = 0; c < 64; c += 4) {
            const float* wp = w0T + c * WSTR + o0;
            ulonglong2 wa0 = *reinterpret_cast<const ulonglong2*>(wp);
            ulonglong2 wa1 = *reinterpret_cast<const ulonglong2*>(wp + 4);
            ulonglong2 wb0 = *reinterpret_cast<const ulonglong2*>(wp + WSTR);
            ulonglong2 wb1 = *reinterpret_cast<const ulonglong2*>(wp + WSTR + 4);
            ulonglong2 wc0 = *reinterpret_cast<const ulonglong2*>(wp + 2 * WSTR);
            ulonglong2 wc1 = *reinterpret_cast<const ulonglong2*>(wp + 2 * WSTR + 4);
            ulonglong2 wd0 = *reinterpret_cast<const ulonglong2*>(wp + 3 * WSTR);
            ulonglong2 wd1 = *reinterpret_cast<const ulonglong2*>(wp + 3 * WSTR + 4);
#pragma unroll
            for (int ki = 0; ki < 8; ki++) {
                float4 hv = *reinterpret_cast<const float4*>(hp2 + ki * HROWS + c);
                ull h0 = pk2(hv.x, hv.x);
                ull h1 = pk2(hv.y, hv.y);
                ull h2 = pk2(hv.z, hv.z);
                ull h3 = pk2(hv.w, hv.w);
                acc[ki][0] = fma2_(h0, wa0.x, acc[ki][0]);
                acc[ki][1] = fma2_(h0, wa0.y, acc[ki][1]);
                acc[ki][2] = fma2_(h0, wa1.x, acc[ki][2]);
                acc[ki][3] = fma2_(h0, wa1.y, acc[ki][3]);
                acc[ki][0] = fma2_(h1, wb0.x, acc[ki][0]);
                acc[ki][1] = fma2_(h1, wb0.y, acc[ki][1]);
                acc[ki][2] = fma2_(h1, wb1.x, acc[ki][2]);
                acc[ki][3] = fma2_(h1, wb1.y, acc[ki][3]);
                acc[ki][0] = fma2_(h2, wc0.x, acc[ki][0]);
                acc[ki][1] = fma2_(h2, wc0.y, acc[ki][1]);
                acc[ki][2] = fma2_(h2, wc1.x, acc[ki][2]);
                acc[ki][3] = fma2_(h2, wc1.y, acc[ki][3]);
                acc[ki][0] = fma2_(h3, wd0.x, acc[ki][0]);
                acc[ki][1] = fma2_(h3, wd0.y, acc[ki][1]);
                acc[ki][2] = fma2_(h3, wd1.x, acc[ki][2]);
                acc[ki][3] = fma2_(h3, wd1.y, acc[ki][3]);
            }
        }
    }
    __syncthreads();
    // leaky + writeback (rows k0..k0+7, cols o0..o0+7)
#pragma unroll
    for (int ki = 0; ki < 8; ki++) {
        float a0, a1, a2, a3, a4, a5, a6, a7;
        upk2(a0, a1, acc[ki][0]);
        upk2(a2, a3, acc[ki][1]);
        upk2(a4, a5, acc[ki][2]);
        upk2(a6, a7, acc[ki][3]);
        float4 v0 = make_float4(leaky(a0), leaky(a1), leaky(a2), leaky(a3));
        float4 v1 = make_float4(leaky(a4), leaky(a5), leaky(a6), leaky(a7));
        *reinterpret_cast<float4*>(hp2 + ki * HROWS + o0)     = v0;
        *reinterpret_cast<float4*>(hp2 + ki * HROWS + o0 + 4) = v1;
    }
    __syncthreads();

    // =============== layer 2 ===============
    {
        ulonglong2 bA = *reinterpret_cast<const ulonglong2*>(b1s + o0);
        ulonglong2 bB = *reinterpret_cast<const ulonglong2*>(b1s + o0 + 4);
#pragma unroll
        for (int ki = 0; ki < 8; ki++) {
            acc[ki][0] = bA.x; acc[ki][1] = bA.y;
            acc[ki][2] = bB.x; acc[ki][3] = bB.y;
        }
#pragma unroll 1
        for (int c = 0; c < 64; c += 4) {
            const float* wp = w1T + c * WSTR + o0;
            ulonglong2 wa0 = *reinterpret_cast<const ulonglong2*>(wp);
            ulonglong2 wa1 = *reinterpret_cast<const ulonglong2*>(wp + 4);
            ulonglong2 wb0 = *reinterpret_cast<const ulonglong2*>(wp + WSTR);
            ulonglong2 wb1 = *reinterpret_cast<const ulonglong2*>(wp + WSTR + 4);
            ulonglong2 wc0 = *reinterpret_cast<const ulonglong2*>(wp + 2 * WSTR);
            ulonglong2 wc1 = *reinterpret_cast<const ulonglong2*>(wp + 2 * WSTR + 4);
            ulonglong2 wd0 = *reinterpret_cast<const ulonglong2*>(wp + 3 * WSTR);
            ulonglong2 wd1 = *reinterpret_cast<const ulonglong2*>(wp + 3 * WSTR + 4);
#pragma unroll
            for (int ki = 0; ki < 8; ki++) {
                float4 hv = *reinterpret_cast<const float4*>(hp2 + ki * HROWS + c);
                ull h0 = pk2(hv.x, hv.x);
                ull h1 = pk2(hv.y, hv.y);
                ull h2 = pk2(hv.z, hv.z);
                ull h3 = pk2(hv.w, hv.w);
                acc[ki][0] = fma2_(h0, wa0.x, acc[ki][0]);
                acc[ki][1] = fma2_(h0, wa0.y, acc[ki][1]);
                acc[ki][2] = fma2_(h0, wa1.x, acc[ki][2]);
                acc[ki][3] = fma2_(h0, wa1.y, acc[ki][3]);
                acc[ki][0] = fma2_(h1, wb0.x, acc[ki][0]);
                acc[ki][1] = fma2_(h1, wb0.y, acc[ki][1]);
                acc[ki][2] = fma2_(h1, wb1.x, acc[ki][2]);
                acc[ki][3] = fma2_(h1, wb1.y, acc[ki][3]);
                acc[ki][0] = fma2_(h2, wc0.x, acc[ki][0]);
                acc[ki][1] = fma2_(h2, wc0.y, acc[ki][1]);
                acc[ki][2] = fma2_(h2, wc1.x, acc[ki][2]);
                acc[ki][3] = fma2_(h2, wc1.y, acc[ki][3]);
                acc[ki][0] = fma2_(h3, wd0.x, acc[ki][0]);
                acc[ki][1] = fma2_(h3, wd0.y, acc[ki][1]);
                acc[ki][2] = fma2_(h3, wd1.x, acc[ki][2]);
                acc[ki][3] = fma2_(h3, wd1.y, acc[ki][3]);
            }
        }
    }

    // leaky + max over this thread's 8 k
    {
        float mx[8];
#pragma unroll
        for (int j = 0; j < 8; j++) mx[j] = -CUDART_INF_F;
#pragma unroll
        for (int ki = 0; ki < 8; ki++) {
            float a0, a1, a2, a3, a4, a5, a6, a7;
            upk2(a0, a1, acc[ki][0]);
            upk2(a2, a3, acc[ki][1]);
            upk2(a4, a5, acc[ki][2]);
            upk2(a6, a7, acc[ki][3]);
            mx[0] = fmaxf(mx[0], leaky(a0));
            mx[1] = fmaxf(mx[1], leaky(a1));
            mx[2] = fmaxf(mx[2], leaky(a2));
            mx[3] = fmaxf(mx[3], leaky(a3));
            mx[4] = fmaxf(mx[4], leaky(a4));
            mx[5] = fmaxf(mx[5], leaky(a5));
            mx[6] = fmaxf(mx[6], leaky(a6));
            mx[7] = fmaxf(mx[7], leaky(a7));
        }
        float* pmp = pm + p * 128 + (k0 >> 3) * 64 + o0;
        *reinterpret_cast<float4*>(pmp)     = make_float4(mx[0], mx[1], mx[2], mx[3]);
        *reinterpret_cast<float4*>(pmp + 4) = make_float4(mx[4], mx[5], mx[6], mx[7]);
    }
    __syncthreads();

    // final max of the 2 k-halves -> g_ms
#pragma unroll
    for (int i = 0; i < 4; i++) {
        int ii = tid + i * 128;
        int pp = ii >> 6, oo = ii & 63;
        float mm = fmaxf(pm[pp * 128 + oo], pm[pp * 128 + 64 + oo]);
        int nn = blockIdx.x * 8 + pp;
        g_ms[((size_t)dirb * NPTS + nn) * CH + oo] = mm;
    }
}

// ---------------------------------------------------------------------------
// proj: block 256 = 128 j x 2 point-halves; 32 points staged per block.
// ---------------------------------------------------------------------------
#define TWSTR 132
__global__ void __launch_bounds__(256) proj_kernel(
        const float* __restrict__ t1w, const float* __restrict__ t1b,
        const float* __restrict__ t2w, const float* __restrict__ t2b,
        float* __restrict__ out) {
    __shared__ float twS[64 * TWSTR];
    __shared__ float tbS[OUTCH];
    __shared__ float aS[32 * 64];

    const int dir = blockIdx.z;
    const int b   = blockIdx.y;
    const int tid = threadIdx.x;
    const int dirb = dir * BATCH + b;

    const float* tw = dir ? t2w : t1w;
    const float* tb = dir ? t2b : t1b;

    // transposed weight load: coalesced float4 read, padded STS
    for (int it = 0; it < 8; it++) {
        int f = tid + it * 256;                 // float4 idx, 2048 total
        float4 a = reinterpret_cast<const float4*>(tw)[f];
        int j = f >> 4, c0 = (f & 15) * 4;
        twS[(c0 + 0) * TWSTR + j] = a.x;
        twS[(c0 + 1) * TWSTR + j] = a.y;
        twS[(c0 + 2) * TWSTR + j] = a.z;
        twS[(c0 + 3) * TWSTR + j] = a.w;
    }
    if (tid < OUTCH) tbS[tid] = tb[tid];

    const int n0 = blockIdx.x * 32;
    for (int i = 0; i < 8; i++) {
        int idx = tid + i * 256;                // 2048 floats
        aS[idx] = g_ms[((size_t)dirb * NPTS + n0 + (idx >> 6)) * CH + (idx & 63)];
    }
    __syncthreads();

    const int j  = tid & 127;
    const int ph = tid >> 7;
#pragma unroll 1
    for (int pi = 0; pi < 16; pi++) {
        int pp = ph * 16 + pi;
        float acc = tbS[j];
        const float* ap = aS + pp * 64;
#pragma unroll
        for (int c = 0; c < 64; c += 4) {
            float4 av = *reinterpret_cast<const float4*>(ap + c);
            acc = fmaf(av.x, twS[(c + 0) * TWSTR + j], acc);
            acc = fmaf(av.y, twS[(c + 1) * TWSTR + j], acc);
            acc = fmaf(av.z, twS[(c + 2) * TWSTR + j], acc);
            acc = fmaf(av.w, twS[(c + 3) * TWSTR + j], acc);
        }
        out[((size_t)dirb * NPTS + n0 + pp) * OUTCH + j] = acc;
    }
}

// ---------------------------------------------------------------------------
extern "C" void kernel_launch(void* const* d_in, const int* in_sizes, int n_in,
                              void* d_out, int out_size) {
    (void)in_sizes; (void)n_in; (void)out_size;
    const float* pc1   = (const float*)d_in[0];
    const float* pc2   = (const float*)d_in[1];
    const float* feat1 = (const float*)d_in[2];
    const float* feat2 = (const float*)d_in[3];
    const float* pos_w = (const float*)d_in[4];
    const float* pos_b = (const float*)d_in[5];
    const float* w0    = (const float*)d_in[6];
    const float* b0    = (const float*)d_in[7];
    const float* w1    = (const float*)d_in[8];
    const float* b1    = (const float*)d_in[9];
    const float* t1w   = (const float*)d_in[10];
    const float* t1b   = (const float*)d_in[11];
    const float* t2w   = (const float*)d_in[12];
    const float* t2b   = (const float*)d_in[13];
    float* out = (float*)d_out;

    pack_kernel<<<(2 * BATCH * NPTS + 255) / 256, 256>>>(pc1, pc2);

    dim3 gk(NPTS / 128, 2 * BATCH, SEG);
    knn_part<<<gk, 128>>>();

    knn_merge<<<(2 * BATCH * NPTS * 32) / 256, 256>>>();

    const size_t smem = (size_t)(64 * WSTR * 2 + 8 * HPNT + 1024 + 192 + 64 * 3)
                        * sizeof(float);
    cudaFuncSetAttribute(feat_kernel,
                         cudaFuncAttributeMaxDynamicSharedMemorySize, (int)smem);
    dim3 gf(NPTS / 8, BATCH, 2);
    feat_kernel<<<gf, 128, smem>>>(feat1, feat2, pos_w, pos_b, w0, b0, w1, b1);

    dim3 gp(NPTS / 32, BATCH, 2);
    proj_kernel<<<gp, 256>>>(t1w, t1b, t2w, t2b, out);
}

// round 5
// speedup vs baseline: 1.7415x; 1.7415x over previous
#include <cuda_runtime.h>
#include <math_constants.h>

#define NSAMPLE 16
#define NPTS    8192
#define BATCH   2
#define CH      64
#define OUTCH   128
#define SEG     2
#define SEGSZ   (NPTS / SEG)      // 4096

typedef unsigned long long ull;
typedef unsigned int uint;

// ---- f32x2 packed helpers (Blackwell) ----
__device__ __forceinline__ ull pk2(float a, float b) {
    ull r; asm("mov.b64 %0,{%1,%2};" : "=l"(r) : "f"(a), "f"(b)); return r;
}
__device__ __forceinline__ void upk2(float& a, float& b, ull r) {
    asm("mov.b64 {%0,%1}, %2;" : "=f"(a), "=f"(b) : "l"(r));
}
__device__ __forceinline__ ull fma2_(ull a, ull b, ull c) {
    ull d; asm("fma.rn.f32x2 %0,%1,%2,%3;" : "=l"(d) : "l"(a), "l"(b), "l"(c)); return d;
}
__device__ __forceinline__ ull add2_(ull a, ull b) {
    ull d; asm("add.rn.f32x2 %0,%1,%2;" : "=l"(d) : "l"(a), "l"(b)); return d;
}
__device__ __forceinline__ ull mul2_(ull a, ull b) {
    ull d; asm("mul.rn.f32x2 %0,%1,%2;" : "=l"(d) : "l"(a), "l"(b)); return d;
}
__device__ __forceinline__ float leaky(float x) { return x >= 0.0f ? x : 0.1f * x; }
__device__ __forceinline__ uint umax_(uint a, uint b) { return a > b ? a : b; }

// scratch
__device__ float4 g_pts4[2 * BATCH * NPTS];
__device__ float2 g_part[2 * BATCH * NPTS * SEG * NSAMPLE];
__device__ int    g_knn[2 * BATCH * NPTS * NSAMPLE];
__device__ float  g_ms[2 * BATCH * NPTS * CH];

// ---------------------------------------------------------------------------
__global__ void pack_kernel(const float* __restrict__ pc1,
                            const float* __restrict__ pc2) {
    int i = blockIdx.x * blockDim.x + threadIdx.x;
    if (i >= 2 * BATCH * NPTS) return;
    const float* src = (i < BATCH * NPTS) ? pc1 : pc2;
    int r = (i < BATCH * NPTS) ? i : (i - BATCH * NPTS);
    float x = src[r * 3 + 0], y = src[r * 3 + 1], z = src[r * 3 + 2];
    g_pts4[i] = make_float4(x, y, z, x * x + y * y + z * z);
}

// ---------------------------------------------------------------------------
// top-16 update: keys = (dist_bits & ~15) | slot  (dist clamped >= 0, so
// unsigned int compare == float compare). Rescan = IMNMX.U32 tree (4cyc,
// alu pipe, no predicates). Replace = key-equality selects (unique key).
// ---------------------------------------------------------------------------
__device__ __forceinline__ void updk(float d, int idx,
                                     uint (&bk)[NSAMPLE], int (&bi)[NSAMPLE],
                                     uint& wdkey, float& wd) {
    d = fmaxf(d, 0.0f);
    uint nk = (__float_as_uint(d) & 0xFFFFFFF0u) | (wdkey & 15u);
#pragma unroll
    for (int k = 0; k < NSAMPLE; k++) {
        bool s = (bk[k] == wdkey);
        bk[k] = s ? nk  : bk[k];
        bi[k] = s ? idx : bi[k];
    }
    uint m0[8];
#pragma unroll
    for (int k = 0; k < 8; k++) m0[k] = umax_(bk[2*k], bk[2*k+1]);
    uint m1[4];
#pragma unroll
    for (int k = 0; k < 4; k++) m1[k] = umax_(m0[2*k], m0[2*k+1]);
    uint m2a = umax_(m1[0], m1[1]);
    uint m2b = umax_(m1[2], m1[3]);
    wdkey = umax_(m2a, m2b);
    wd = __uint_as_float(wdkey & 0xFFFFFFF0u);
}

// ---------------------------------------------------------------------------
// KNN pass 1: per (query, segment) top-16 over 4096 candidates.
// ---------------------------------------------------------------------------
__global__ void __launch_bounds__(256) knn_part() {
    extern __shared__ float ks[];
    float* sx = ks;
    float* sy = sx + SEGSZ;
    float* sz = sy + SEGSZ;
    float* sw = sz + SEGSZ;

    const int dirb = blockIdx.y;               // dir*2 + b
    const int dir  = dirb >> 1;
    const int b    = dirb & 1;
    const int seg  = blockIdx.z;
    const int n    = blockIdx.x * 256 + threadIdx.x;

    const float4* Qb = g_pts4 + ((size_t)dir * BATCH + b) * NPTS;
    const float4* Cb = g_pts4 + ((size_t)(1 - dir) * BATCH + b) * NPTS + seg * SEGSZ;

    for (int i = threadIdx.x; i < SEGSZ; i += 256) {
        float4 c = Cb[i];
        sx[i] = c.x; sy[i] = c.y; sz[i] = c.z; sw[i] = c.w;
    }
    __syncthreads();

    const float4 q = Qb[n];
    const ull qx2 = pk2(q.x, q.x);
    const ull qy2 = pk2(q.y, q.y);
    const ull qz2 = pk2(q.z, q.z);
    const ull sq2 = pk2(q.w, q.w);
    const ull m2  = pk2(-2.0f, -2.0f);

    uint bk[NSAMPLE]; int bi[NSAMPLE];
#pragma unroll
    for (int k = 0; k < NSAMPLE; k++) { bk[k] = 0x7F800000u | k; bi[k] = 0; }
    uint wdkey = 0x7F80000Fu;
    float wd   = CUDART_INF_F;
    const int base = seg * SEGSZ;

#pragma unroll 1
    for (int j = 0; j < SEGSZ; j += 4) {
        ulonglong2 X = *reinterpret_cast<const ulonglong2*>(&sx[j]);
        ulonglong2 Y = *reinterpret_cast<const ulonglong2*>(&sy[j]);
        ulonglong2 Z = *reinterpret_cast<const ulonglong2*>(&sz[j]);
        ulonglong2 W = *reinterpret_cast<const ulonglong2*>(&sw[j]);
        ull t01 = fma2_(qx2, X.x, fma2_(qy2, Y.x, mul2_(qz2, Z.x)));
        ull t23 = fma2_(qx2, X.y, fma2_(qy2, Y.y, mul2_(qz2, Z.y)));
        ull d01 = fma2_(m2, t01, add2_(sq2, W.x));
        ull d23 = fma2_(m2, t23, add2_(sq2, W.y));
        float d0, d1, d2, d3;
        upk2(d0, d1, d01);
        upk2(d2, d3, d23);
        if (d0 < wd) updk(d0, base + j + 0, bk, bi, wdkey, wd);
        if (d1 < wd) updk(d1, base + j + 1, bk, bi, wdkey, wd);
        if (d2 < wd) updk(d2, base + j + 2, bk, bi, wdkey, wd);
        if (d3 < wd) updk(d3, base + j + 3, bk, bi, wdkey, wd);
    }

    float2* outp = g_part + (((size_t)dirb * NPTS + n) * SEG + seg) * NSAMPLE;
#pragma unroll
    for (int k = 0; k < NSAMPLE; k++)
        outp[k] = make_float2(__uint_as_float(bk[k] & 0xFFFFFFF0u),
                              __int_as_float(bi[k]));
}

// ---------------------------------------------------------------------------
// KNN pass 2: warp per query merges 2x16 (one entry/lane) -> exact top-16.
// ---------------------------------------------------------------------------
__global__ void __launch_bounds__(256) knn_merge() {
    const int gtid = blockIdx.x * 256 + threadIdx.x;
    const int q    = gtid >> 5;
    const int lane = gtid & 31;

    float2 e = g_part[(size_t)q * (SEG * NSAMPLE) + lane];
    float d = e.x; int i = __float_as_int(e.y);

    int* outp = g_knn + (size_t)q * NSAMPLE;

#pragma unroll
    for (int k = 0; k < NSAMPLE; k++) {
        float bdv = d;
        int   biv = i;
#pragma unroll
        for (int off = 16; off > 0; off >>= 1) {
            float od = __shfl_xor_sync(0xFFFFFFFFu, bdv, off);
            int   oi = __shfl_xor_sync(0xFFFFFFFFu, biv, off);
            if (od < bdv || (od == bdv && oi < biv)) { bdv = od; biv = oi; }
        }
        if (lane == 0) outp[k] = biv;
        if (d == bdv && i == biv) d = CUDART_INF_F;
    }
}

// ---------------------------------------------------------------------------
// feat: 128 threads = 8 points x 16 threads; k8 x o8 f32x2 tiles.
// pm aliases hs (dead after layer 2) -> 72.4KB smem -> 3 blocks/SM.
// ---------------------------------------------------------------------------
#define WSTR 68
#define HROWS 68
#define HPNT  1128

__device__ __forceinline__ int hoff(int p, int k) {
    return p * HPNT + k * HROWS + ((k >> 3) << 4);
}

__global__ void __launch_bounds__(128, 3) feat_kernel(
        const float* __restrict__ feat1,
        const float* __restrict__ feat2,
        const float* __restrict__ pos_w,
        const float* __restrict__ pos_b,
        const float* __restrict__ w0,
        const float* __restrict__ b0,
        const float* __restrict__ w1,
        const float* __restrict__ b1) {
    extern __shared__ float sm[];
    float* w0T   = sm;                         // 4352
    float* w1T   = w0T + 64 * WSTR;            // 4352
    float* hs    = w1T + 64 * WSTR;            // 9024
    float* pm    = hs;                         // ALIAS: hs dead after layer 2
    float* posws = hs + 8 * HPNT;              // 192
    float* posbs = posws + 192;                // 64
    float* b0s   = posbs + 64;                 // 64
    float* b1s   = b0s + 64;                   // 64

    const int dir = blockIdx.z;
    const int b   = blockIdx.y;
    const int tid = threadIdx.x;
    const int dirb = dir * BATCH + b;

    for (int it = 0; it < 8; it++) {
        int f = tid + it * 128;
        float4 a = reinterpret_cast<const float4*>(w0)[f];
        float4 c = reinterpret_cast<const float4*>(w1)[f];
        int o = f >> 4, c0 = (f & 15) * 4;
        w0T[(c0 + 0) * WSTR + o] = a.x;
        w0T[(c0 + 1) * WSTR + o] = a.y;
        w0T[(c0 + 2) * WSTR + o] = a.z;
        w0T[(c0 + 3) * WSTR + o] = a.w;
        w1T[(c0 + 0) * WSTR + o] = c.x;
        w1T[(c0 + 1) * WSTR + o] = c.y;
        w1T[(c0 + 2) * WSTR + o] = c.z;
        w1T[(c0 + 3) * WSTR + o] = c.w;
    }
    if (tid < 64) {
        posbs[tid] = pos_b[tid];
        b0s[tid]   = b0[tid];
        b1s[tid]   = b1[tid];
    }
    for (int i = tid; i < 192; i += 128) posws[i] = pos_w[i];
    __syncthreads();

    const float* F1 = dir ? feat2 : feat1;
    const float* F2 = dir ? feat1 : feat2;
    const float4* QC = g_pts4 + ((size_t)dir * BATCH + b) * NPTS;
    const float4* NC = g_pts4 + ((size_t)(1 - dir) * BATCH + b) * NPTS;

    // ---- stage 1: gather + pos feat + leaky -> hs ----
    {
        const int c  = tid & 63;
        const int rh = tid >> 6;
        const float pwx = posws[c * 3 + 0];
        const float pwy = posws[c * 3 + 1];
        const float pwz = posws[c * 3 + 2];
        const float pb  = posbs[c];
        for (int it = 0; it < 64; it++) {
            int row = it * 2 + rh;
            int p = row >> 4, k = row & 15;
            int n = blockIdx.x * 8 + p;
            int id = g_knn[((size_t)dirb * NPTS + n) * NSAMPLE + k];
            float4 cc = NC[id];
            float4 qq = QC[n];
            float g   = F2[((size_t)b * NPTS + id) * CH + c];
            float p1o = F1[((size_t)b * NPTS + n) * CH + c];
            float h = g + p1o +
                fmaf(pwx, cc.x - qq.x, fmaf(pwy, cc.y - qq.y,
                fmaf(pwz, cc.z - qq.z, pb)));
            hs[hoff(p, k) + c] = leaky(h);
        }
    }
    __syncthreads();

    const int tt = tid & 15;
    const int p  = tid >> 4;
    const int o0 = (tt & 7) * 8;
    const int k0 = (tt >> 3) * 8;
    float* hp2 = hs + hoff(p, k0);

    ull acc[8][4];

    // =============== layer 1 ===============
    {
        ulonglong2 bA = *reinterpret_cast<const ulonglong2*>(b0s + o0);
        ulonglong2 bB = *reinterpret_cast<const ulonglong2*>(b0s + o0 + 4);
#pragma unroll
        for (int ki = 0; ki < 8; ki++) {
            acc[ki][0] = bA.x; acc[ki][1] = bA.y;
            acc[ki][2] = bB.x; acc[ki][3] = bB.y;
        }
#pragma unroll 1
        for (int c = 0; c < 64; c += 4) {
            const float* wp = w0T + c * WSTR + o0;
            ulonglong2 wa0 = *reinterpret_cast<const ulonglong2*>(wp);
            ulonglong2 wa1 = *reinterpret_cast<const ulonglong2*>(wp + 4);
            ulonglong2 wb0 = *reinterpret_cast<const ulonglong2*>(wp + WSTR);
            ulonglong2 wb1 = *reinterpret_cast<const ulonglong2*>(wp + WSTR + 4);
            ulonglong2 wc0 = *reinterpret_cast<const ulonglong2*>(wp + 2 * WSTR);
            ulonglong2 wc1 = *reinterpret_cast<const ulonglong2*>(wp + 2 * WSTR + 4);
            ulonglong2 wd0 = *reinterpret_cast<const ulonglong2*>(wp + 3 * WSTR);
            ulonglong2 wd1 = *reinterpret_cast<const ulonglong2*>(wp + 3 * WSTR + 4);
#pragma unroll
            for (int ki = 0; ki < 8; ki++) {
                float4 hv = *reinterpret_cast<const float4*>(hp2 + ki * HROWS + c);
                ull h0 = pk2(hv.x, hv.x);
                ull h1 = pk2(hv.y, hv.y);
                ull h2 = pk2(hv.z, hv.z);
                ull h3 = pk2(hv.w, hv.w);
                acc[ki][0] = fma2_(h0, wa0.x, acc[ki][0]);
                acc[ki][1] = fma2_(h0, wa0.y, acc[ki][1]);
                acc[ki][2] = fma2_(h0, wa1.x, acc[ki][2]);
                acc[ki][3] = fma2_(h0, wa1.y, acc[ki][3]);
                acc[ki][0] = fma2_(h1, wb0.x, acc[ki][0]);
                acc[ki][1] = fma2_(h1, wb0.y, acc[ki][1]);
                acc[ki][2] = fma2_(h1, wb1.x, acc[ki][2]);
                acc[ki][3] = fma2_(h1, wb1.y, acc[ki][3]);
                acc[ki][0] = fma2_(h2, wc0.x, acc[ki][0]);
                acc[ki][1] = fma2_(h2, wc0.y, acc[ki][1]);
                acc[ki][2] = fma2_(h2, wc1.x, acc[ki][2]);
                acc[ki][3] = fma2_(h2, wc1.y, acc[ki][3]);
                acc[ki][0] = fma2_(h3, wd0.x, acc[ki][0]);
                acc[ki][1] = fma2_(h3, wd0.y, acc[ki][1]);
                acc[ki][2] = fma2_(h3, wd1.x, acc[ki][2]);
                acc[ki][3] = fma2_(h3, wd1.y, acc[ki][3]);
            }
        }
    }
    __syncthreads();
#pragma unroll
    for (int ki = 0; ki < 8; ki++) {
        float a0, a1, a2, a3, a4, a5, a6, a7;
        upk2(a0, a1, acc[ki][0]);
        upk2(a2, a3, acc[ki][1]);
        upk2(a4, a5, acc[ki][2]);
        upk2(a6, a7, acc[ki][3]);
        float4 v0 = make_float4(leaky(a0), leaky(a1), leaky(a2), leaky(a3));
        float4 v1 = make_float4(leaky(a4), leaky(a5), leaky(a6), leaky(a7));
        *reinterpret_cast<float4*>(hp2 + ki * HROWS + o0)     = v0;
        *reinterpret_cast<float4*>(hp2 + ki * HROWS + o0 + 4) = v1;
    }
    __syncthreads();

    // =============== layer 2 ===============
    {
        ulonglong2 bA = *reinterpret_cast<const ulonglong2*>(b1s + o0);
        ulonglong2 bB = *reinterpret_cast<const ulonglong2*>(b1s + o0 + 4);
#pragma unroll
        for (int ki = 0; ki < 8; ki++) {
            acc[ki][0] = bA.x; acc[ki][1] = bA.y;
            acc[ki][2] = bB.x; acc[ki][3] = bB.y;
        }
#pragma unroll 1
        for (int c = 0; c < 64; c += 4) {
            const float* wp = w1T + c * WSTR + o0;
            ulonglong2 wa0 = *reinterpret_cast<const ulonglong2*>(wp);
            ulonglong2 wa1 = *reinterpret_cast<const ulonglong2*>(wp + 4);
            ulonglong2 wb0 = *reinterpret_cast<const ulonglong2*>(wp + WSTR);
            ulonglong2 wb1 = *reinterpret_cast<const ulonglong2*>(wp + WSTR + 4);
            ulonglong2 wc0 = *reinterpret_cast<const ulonglong2*>(wp + 2 * WSTR);
            ulonglong2 wc1 = *reinterpret_cast<const ulonglong2*>(wp + 2 * WSTR + 4);
            ulonglong2 wd0 = *reinterpret_cast<const ulonglong2*>(wp + 3 * WSTR);
            ulonglong2 wd1 = *reinterpret_cast<const ulonglong2*>(wp + 3 * WSTR + 4);
#pragma unroll
            for (int ki = 0; ki < 8; ki++) {
                float4 hv = *reinterpret_cast<const float4*>(hp2 + ki * HROWS + c);
                ull h0 = pk2(hv.x, hv.x);
                ull h1 = pk2(hv.y, hv.y);
                ull h2 = pk2(hv.z, hv.z);
                ull h3 = pk2(hv.w, hv.w);
                acc[ki][0] = fma2_(h0, wa0.x, acc[ki][0]);
                acc[ki][1] = fma2_(h0, wa0.y, acc[ki][1]);
                acc[ki][2] = fma2_(h0, wa1.x, acc[ki][2]);
                acc[ki][3] = fma2_(h0, wa1.y, acc[ki][3]);
                acc[ki][0] = fma2_(h1, wb0.x, acc[ki][0]);
                acc[ki][1] = fma2_(h1, wb0.y, acc[ki][1]);
                acc[ki][2] = fma2_(h1, wb1.x, acc[ki][2]);
                acc[ki][3] = fma2_(h1, wb1.y, acc[ki][3]);
                acc[ki][0] = fma2_(h2, wc0.x, acc[ki][0]);
                acc[ki][1] = fma2_(h2, wc0.y, acc[ki][1]);
                acc[ki][2] = fma2_(h2, wc1.x, acc[ki][2]);
                acc[ki][3] = fma2_(h2, wc1.y, acc[ki][3]);
                acc[ki][0] = fma2_(h3, wd0.x, acc[ki][0]);
                acc[ki][1] = fma2_(h3, wd0.y, acc[ki][1]);
                acc[ki][2] = fma2_(h3, wd1.x, acc[ki][2]);
                acc[ki][3] = fma2_(h3, wd1.y, acc[ki][3]);
            }
        }
    }

    // hs is dead from here; pm aliases it — barrier before reuse
    __syncthreads();

    {
        float mx[8];
#pragma unroll
        for (int j = 0; j < 8; j++) mx[j] = -CUDART_INF_F;
#pragma unroll
        for (int ki = 0; ki < 8; ki++) {
            float a0, a1, a2, a3, a4, a5, a6, a7;
            upk2(a0, a1, acc[ki][0]);
            upk2(a2, a3, acc[ki][1]);
            upk2(a4, a5, acc[ki][2]);
            upk2(a6, a7, acc[ki][3]);
            mx[0] = fmaxf(mx[0], leaky(a0));
            mx[1] = fmaxf(mx[1], leaky(a1));
            mx[2] = fmaxf(mx[2], leaky(a2));
            mx[3] = fmaxf(mx[3], leaky(a3));
            mx[4] = fmaxf(mx[4], leaky(a4));
            mx[5] = fmaxf(mx[5], leaky(a5));
            mx[6] = fmaxf(mx[6], leaky(a6));
            mx[7] = fmaxf(mx[7], leaky(a7));
        }
        float* pmp = pm + p * 128 + (k0 >> 3) * 64 + o0;
        *reinterpret_cast<float4*>(pmp)     = make_float4(mx[0], mx[1], mx[2], mx[3]);
        *reinterpret_cast<float4*>(pmp + 4) = make_float4(mx[4], mx[5], mx[6], mx[7]);
    }
    __syncthreads();

#pragma unroll
    for (int i = 0; i < 4; i++) {
        int ii = tid + i * 128;
        int pp = ii >> 6, oo = ii & 63;
        float mm = fmaxf(pm[pp * 128 + oo], pm[pp * 128 + 64 + oo]);
        int nn = blockIdx.x * 8 + pp;
        g_ms[((size_t)dirb * NPTS + nn) * CH + oo] = mm;
    }
}

// ---------------------------------------------------------------------------
// proj: 128 threads = 128 output channels; weight row (64fl) in registers,
// 64 points staged in smem, broadcast LDS.128 activations.
// ---------------------------------------------------------------------------
#define PPROJ 64
__global__ void __launch_bounds__(128) proj_kernel(
        const float* __restrict__ t1w, const float* __restrict__ t1b,
        const float* __restrict__ t2w, const float* __restrict__ t2b,
        float* __restrict__ out) {
    __shared__ float aS[PPROJ * 64];

    const int dir = blockIdx.z;
    const int b   = blockIdx.y;
    const int j   = threadIdx.x;        // output channel
    const int dirb = dir * BATCH + b;

    const float* tw = dir ? t2w : t1w;
    const float* tb = dir ? t2b : t1b;

    // per-thread weight row -> registers (L1/L2 cached across blocks)
    float4 w[16];
#pragma unroll
    for (int t = 0; t < 16; t++)
        w[t] = reinterpret_cast<const float4*>(tw + j * 64)[t];
    const float bias = tb[j];

    const int n0 = blockIdx.x * PPROJ;
    // stage activations: PPROJ*64 floats, coalesced
#pragma unroll
    for (int i = 0; i < PPROJ * 64 / 128 / 4; i++) {   // 8 float4 per thread
        int f = j + i * 128;
        reinterpret_cast<float4*>(aS)[f] =
            reinterpret_cast<const float4*>(g_ms + ((size_t)dirb * NPTS + n0) * CH)[f];
    }
    __syncthreads();

#pragma unroll 2
    for (int p = 0; p < PPROJ; p++) {
        float acc = bias;
        const float4* ap = reinterpret_cast<const float4*>(aS + p * 64);
#pragma unroll
        for (int t = 0; t < 16; t++) {
            float4 a = ap[t];
            acc = fmaf(a.x, w[t].x, acc);
            acc = fmaf(a.y, w[t].y, acc);
            acc = fmaf(a.z, w[t].z, acc);
            acc = fmaf(a.w, w[t].w, acc);
        }
        out[((size_t)dirb * NPTS + n0 + p) * OUTCH + j] = acc;
    }
}

// ---------------------------------------------------------------------------
extern "C" void kernel_launch(void* const* d_in, const int* in_sizes, int n_in,
                              void* d_out, int out_size) {
    (void)in_sizes; (void)n_in; (void)out_size;
    const float* pc1   = (const float*)d_in[0];
    const float* pc2   = (const float*)d_in[1];
    const float* feat1 = (const float*)d_in[2];
    const float* feat2 = (const float*)d_in[3];
    const float* pos_w = (const float*)d_in[4];
    const float* pos_b = (const float*)d_in[5];
    const float* w0    = (const float*)d_in[6];
    const float* b0    = (const float*)d_in[7];
    const float* w1    = (const float*)d_in[8];
    const float* b1    = (const float*)d_in[9];
    const float* t1w   = (const float*)d_in[10];
    const float* t1b   = (const float*)d_in[11];
    const float* t2w   = (const float*)d_in[12];
    const float* t2b   = (const float*)d_in[13];
    float* out = (float*)d_out;

    pack_kernel<<<(2 * BATCH * NPTS + 255) / 256, 256>>>(pc1, pc2);

    const size_t ksmem = 4 * SEGSZ * sizeof(float);   // 64KB
    cudaFuncSetAttribute(knn_part,
                         cudaFuncAttributeMaxDynamicSharedMemorySize, (int)ksmem);
    dim3 gk(NPTS / 256, 2 * BATCH, SEG);
    knn_part<<<gk, 256, ksmem>>>();

    knn_merge<<<(2 * BATCH * NPTS * 32) / 256, 256>>>();

    const size_t smem = (size_t)(64 * WSTR * 2 + 8 * HPNT + 192 + 64 * 3)
                        * sizeof(float);
    cudaFuncSetAttribute(feat_kernel,
                         cudaFuncAttributeMaxDynamicSharedMemorySize, (int)smem);
    dim3 gf(NPTS / 8, BATCH, 2);
    feat_kernel<<<gf, 128, smem>>>(feat1, feat2, pos_w, pos_b, w0, b0, w1, b1);

    dim3 gp(NPTS / PPROJ, BATCH, 2);
    proj_kernel<<<gp, 128>>>(t1w, t1b, t2w, t2b, out);
}

// round 7
// speedup vs baseline: 1.9441x; 1.1163x over previous
#include <cuda_runtime.h>
#include <math_constants.h>

#define NSAMPLE 16
#define NPTS    8192
#define BATCH   2
#define CH      64
#define OUTCH   128
#define SEG     2
#define SEGSZ   (NPTS / SEG)      // 4096
#define KBT     256               // knn block threads

typedef unsigned long long ull;
typedef unsigned int uint;

// ---- f32x2 packed helpers (Blackwell) ----
__device__ __forceinline__ ull pk2(float a, float b) {
    ull r; asm("mov.b64 %0,{%1,%2};" : "=l"(r) : "f"(a), "f"(b)); return r;
}
__device__ __forceinline__ void upk2(float& a, float& b, ull r) {
    asm("mov.b64 {%0,%1}, %2;" : "=f"(a), "=f"(b) : "l"(r));
}
__device__ __forceinline__ ull fma2_(ull a, ull b, ull c) {
    ull d; asm("fma.rn.f32x2 %0,%1,%2,%3;" : "=l"(d) : "l"(a), "l"(b), "l"(c)); return d;
}
__device__ __forceinline__ ull add2_(ull a, ull b) {
    ull d; asm("add.rn.f32x2 %0,%1,%2;" : "=l"(d) : "l"(a), "l"(b)); return d;
}
__device__ __forceinline__ ull mul2_(ull a, ull b) {
    ull d; asm("mul.rn.f32x2 %0,%1,%2;" : "=l"(d) : "l"(a), "l"(b)); return d;
}
__device__ __forceinline__ float leaky(float x) { return x >= 0.0f ? x : 0.1f * x; }
__device__ __forceinline__ uint umax_(uint a, uint b) { return a > b ? a : b; }

// scratch
__device__ float4 g_pts4[2 * BATCH * NPTS];
__device__ float2 g_part[2 * BATCH * NPTS * SEG * NSAMPLE];
__device__ int    g_knn[2 * BATCH * NPTS * NSAMPLE];
__device__ float  g_ms[2 * BATCH * NPTS * CH];

// ---------------------------------------------------------------------------
__global__ void pack_kernel(const float* __restrict__ pc1,
                            const float* __restrict__ pc2) {
    int i = blockIdx.x * blockDim.x + threadIdx.x;
    if (i >= 2 * BATCH * NPTS) return;
    const float* src = (i < BATCH * NPTS) ? pc1 : pc2;
    int r = (i < BATCH * NPTS) ? i : (i - BATCH * NPTS);
    float x = src[r * 3 + 0], y = src[r * 3 + 1], z = src[r * 3 + 2];
    g_pts4[i] = make_float4(x, y, z, x * x + y * y + z * z);
}

// ---------------------------------------------------------------------------
// KNN pass 1. Top-16 kept as 16 uint keys (dist bits with low 4 bits = slot,
// dist clamped >= 0 so uint order == float order). Per hit: replace the
// slot whose key == wdkey (16 ISETP+SEL), store idx to slot-major smem
// (1 conflict-free STS), rescan via 15-IMNMX tree. No index register array.
// NOTE: wd MUST be reconstructed with the slot bits masked off — initial
// keys 0x7F80000k (k>0) are NaN if interpreted raw (R6 bug).
// ---------------------------------------------------------------------------
__global__ void __launch_bounds__(KBT) knn_part() {
    extern __shared__ float ks[];
    float* sx = ks;
    float* sy = sx + SEGSZ;
    float* sz = sy + SEGSZ;
    float* sw = sz + SEGSZ;
    int*   sidx = (int*)(sw + SEGSZ);        // [16][KBT]

    const int dirb = blockIdx.y;             // dir*2 + b
    const int dir  = dirb >> 1;
    const int b    = dirb & 1;
    const int seg  = blockIdx.z;
    const int tid  = threadIdx.x;
    const int n    = blockIdx.x * KBT + tid;

    const float4* Qb = g_pts4 + ((size_t)dir * BATCH + b) * NPTS;
    const float4* Cb = g_pts4 + ((size_t)(1 - dir) * BATCH + b) * NPTS + seg * SEGSZ;

    // init slot-major index store (safety: never read garbage)
#pragma unroll
    for (int k = 0; k < NSAMPLE; k++) sidx[k * KBT + tid] = 0;

    for (int i = tid; i < SEGSZ; i += KBT) {
        float4 c = Cb[i];
        sx[i] = c.x; sy[i] = c.y; sz[i] = c.z; sw[i] = c.w;
    }
    __syncthreads();

    const float4 q = Qb[n];
    const ull qx2 = pk2(q.x, q.x);
    const ull qy2 = pk2(q.y, q.y);
    const ull qz2 = pk2(q.z, q.z);
    const ull sq2 = pk2(q.w, q.w);
    const ull m2  = pk2(-2.0f, -2.0f);

    uint bk[NSAMPLE];
#pragma unroll
    for (int k = 0; k < NSAMPLE; k++) bk[k] = 0x7F800000u | k;
    uint wdkey = 0x7F80000Fu;
    float wd   = CUDART_INF_F;
    const int base = seg * SEGSZ;

#pragma unroll 1
    for (int j = 0; j < SEGSZ; j += 4) {
        ulonglong2 X = *reinterpret_cast<const ulonglong2*>(&sx[j]);
        ulonglong2 Y = *reinterpret_cast<const ulonglong2*>(&sy[j]);
        ulonglong2 Z = *reinterpret_cast<const ulonglong2*>(&sz[j]);
        ulonglong2 W = *reinterpret_cast<const ulonglong2*>(&sw[j]);
        ull t01 = fma2_(qx2, X.x, fma2_(qy2, Y.x, mul2_(qz2, Z.x)));
        ull t23 = fma2_(qx2, X.y, fma2_(qy2, Y.y, mul2_(qz2, Z.y)));
        ull d01 = fma2_(m2, t01, add2_(sq2, W.x));
        ull d23 = fma2_(m2, t23, add2_(sq2, W.y));
        float d0, d1, d2, d3;
        upk2(d0, d1, d01);
        upk2(d2, d3, d23);
        float m4 = fminf(fminf(d0, d1), fminf(d2, d3));
        if (m4 < wd) {
#pragma unroll
            for (int t = 0; t < 4; t++) {
                float d = (t == 0) ? d0 : (t == 1) ? d1 : (t == 2) ? d2 : d3;
                if (d < wd) {
                    uint slot = wdkey & 15u;
                    uint nk = (__float_as_uint(fmaxf(d, 0.0f)) & 0xFFFFFFF0u) | slot;
                    sidx[slot * KBT + tid] = base + j + t;
#pragma unroll
                    for (int k = 0; k < NSAMPLE; k++)
                        bk[k] = (bk[k] == wdkey) ? nk : bk[k];
                    uint m0[8];
#pragma unroll
                    for (int k = 0; k < 8; k++) m0[k] = umax_(bk[2*k], bk[2*k+1]);
                    uint m1[4];
#pragma unroll
                    for (int k = 0; k < 4; k++) m1[k] = umax_(m0[2*k], m0[2*k+1]);
                    wdkey = umax_(umax_(m1[0], m1[1]), umax_(m1[2], m1[3]));
                    wd = __uint_as_float(wdkey & 0xFFFFFFF0u);   // mask slot bits!
                }
            }
        }
    }

    float2* outp = g_part + (((size_t)dirb * NPTS + n) * SEG + seg) * NSAMPLE;
#pragma unroll
    for (int k = 0; k < NSAMPLE; k++) {
        int idx = sidx[(bk[k] & 15u) * KBT + tid];
        outp[k] = make_float2(__uint_as_float(bk[k] & 0xFFFFFFF0u),
                              __int_as_float(idx));
    }
}

// ---------------------------------------------------------------------------
// KNN pass 2: warp per query merges 2x16 (one entry/lane) -> exact top-16.
// ---------------------------------------------------------------------------
__global__ void __launch_bounds__(256) knn_merge() {
    const int gtid = blockIdx.x * 256 + threadIdx.x;
    const int q    = gtid >> 5;
    const int lane = gtid & 31;

    float2 e = g_part[(size_t)q * (SEG * NSAMPLE) + lane];
    float d = e.x; int i = __float_as_int(e.y);

    int* outp = g_knn + (size_t)q * NSAMPLE;

#pragma unroll
    for (int k = 0; k < NSAMPLE; k++) {
        float bdv = d;
        int   biv = i;
#pragma unroll
        for (int off = 16; off > 0; off >>= 1) {
            float od = __shfl_xor_sync(0xFFFFFFFFu, bdv, off);
            int   oi = __shfl_xor_sync(0xFFFFFFFFu, biv, off);
            if (od < bdv || (od == bdv && oi < biv)) { bdv = od; biv = oi; }
        }
        if (lane == 0) outp[k] = biv;
        if (d == bdv && i == biv) d = CUDART_INF_F;
    }
}

// ---------------------------------------------------------------------------
// feat: 128 threads = 8 points x 16 threads; k8 x o8 f32x2 tiles.
// pm aliases hs (dead after layer 2) -> 72.4KB smem -> 3 blocks/SM.
// ---------------------------------------------------------------------------
#define WSTR 68
#define HROWS 68
#define HPNT  1128

__device__ __forceinline__ int hoff(int p, int k) {
    return p * HPNT + k * HROWS + ((k >> 3) << 4);
}

__global__ void __launch_bounds__(128, 3) feat_kernel(
        const float* __restrict__ feat1,
        const float* __restrict__ feat2,
        const float* __restrict__ pos_w,
        const float* __restrict__ pos_b,
        const float* __restrict__ w0,
        const float* __restrict__ b0,
        const float* __restrict__ w1,
        const float* __restrict__ b1) {
    extern __shared__ float sm[];
    float* w0T   = sm;                         // 4352
    float* w1T   = w0T + 64 * WSTR;            // 4352
    float* hs    = w1T + 64 * WSTR;            // 9024
    float* pm    = hs;                         // ALIAS: hs dead after layer 2
    float* posws = hs + 8 * HPNT;              // 192
    float* posbs = posws + 192;                // 64
    float* b0s   = posbs + 64;                 // 64
    float* b1s   = b0s + 64;                   // 64

    const int dir = blockIdx.z;
    const int b   = blockIdx.y;
    const int tid = threadIdx.x;
    const int dirb = dir * BATCH + b;

    for (int it = 0; it < 8; it++) {
        int f = tid + it * 128;
        float4 a = reinterpret_cast<const float4*>(w0)[f];
        float4 c = reinterpret_cast<const float4*>(w1)[f];
        int o = f >> 4, c0 = (f & 15) * 4;
        w0T[(c0 + 0) * WSTR + o] = a.x;
        w0T[(c0 + 1) * WSTR + o] = a.y;
        w0T[(c0 + 2) * WSTR + o] = a.z;
        w0T[(c0 + 3) * WSTR + o] = a.w;
        w1T[(c0 + 0) * WSTR + o] = c.x;
        w1T[(c0 + 1) * WSTR + o] = c.y;
        w1T[(c0 + 2) * WSTR + o] = c.z;
        w1T[(c0 + 3) * WSTR + o] = c.w;
    }
    if (tid < 64) {
        posbs[tid] = pos_b[tid];
        b0s[tid]   = b0[tid];
        b1s[tid]   = b1[tid];
    }
    for (int i = tid; i < 192; i += 128) posws[i] = pos_w[i];
    __syncthreads();

    const float* F1 = dir ? feat2 : feat1;
    const float* F2 = dir ? feat1 : feat2;
    const float4* QC = g_pts4 + ((size_t)dir * BATCH + b) * NPTS;
    const float4* NC = g_pts4 + ((size_t)(1 - dir) * BATCH + b) * NPTS;

    // ---- stage 1: gather + pos feat + leaky -> hs ----
    {
        const int c  = tid & 63;
        const int rh = tid >> 6;
        const float pwx = posws[c * 3 + 0];
        const float pwy = posws[c * 3 + 1];
        const float pwz = posws[c * 3 + 2];
        const float pb  = posbs[c];
        for (int it = 0; it < 64; it++) {
            int row = it * 2 + rh;
            int p = row >> 4, k = row & 15;
            int n = blockIdx.x * 8 + p;
            int id = g_knn[((size_t)dirb * NPTS + n) * NSAMPLE + k];
            float4 cc = NC[id];
            float4 qq = QC[n];
            float g   = F2[((size_t)b * NPTS + id) * CH + c];
            float p1o = F1[((size_t)b * NPTS + n) * CH + c];
            float h = g + p1o +
                fmaf(pwx, cc.x - qq.x, fmaf(pwy, cc.y - qq.y,
                fmaf(pwz, cc.z - qq.z, pb)));
            hs[hoff(p, k) + c] = leaky(h);
        }
    }
    __syncthreads();

    const int tt = tid & 15;
    const int p  = tid >> 4;
    const int o0 = (tt & 7) * 8;
    const int k0 = (tt >> 3) * 8;
    float* hp2 = hs + hoff(p, k0);

    ull acc[8][4];

    // =============== layer 1 ===============
    {
        ulonglong2 bA = *reinterpret_cast<const ulonglong2*>(b0s + o0);
        ulonglong2 bB = *reinterpret_cast<const ulonglong2*>(b0s + o0 + 4);
#pragma unroll
        for (int ki = 0; ki < 8; ki++) {
            acc[ki][0] = bA.x; acc[ki][1] = bA.y;
            acc[ki][2] = bB.x; acc[ki][3] = bB.y;
        }
#pragma unroll 1
        for (int c = 0; c < 64; c += 4) {
            const float* wp = w0T + c * WSTR + o0;
            ulonglong2 wa0 = *reinterpret_cast<const ulonglong2*>(wp);
            ulonglong2 wa1 = *reinterpret_cast<const ulonglong2*>(wp + 4);
            ulonglong2 wb0 = *reinterpret_cast<const ulonglong2*>(wp + WSTR);
            ulonglong2 wb1 = *reinterpret_cast<const ulonglong2*>(wp + WSTR + 4);
            ulonglong2 wc0 = *reinterpret_cast<const ulonglong2*>(wp + 2 * WSTR);
            ulonglong2 wc1 = *reinterpret_cast<const ulonglong2*>(wp + 2 * WSTR + 4);
            ulonglong2 wd0 = *reinterpret_cast<const ulonglong2*>(wp + 3 * WSTR);
            ulonglong2 wd1 = *reinterpret_cast<const ulonglong2*>(wp + 3 * WSTR + 4);
#pragma unroll
            for (int ki = 0; ki < 8; ki++) {
                float4 hv = *reinterpret_cast<const float4*>(hp2 + ki * HROWS + c);
                ull h0 = pk2(hv.x, hv.x);
                ull h1 = pk2(hv.y, hv.y);
                ull h2 = pk2(hv.z, hv.z);
                ull h3 = pk2(hv.w, hv.w);
                acc[ki][0] = fma2_(h0, wa0.x, acc[ki][0]);
                acc[ki][1] = fma2_(h0, wa0.y, acc[ki][1]);
                acc[ki][2] = fma2_(h0, wa1.x, acc[ki][2]);
                acc[ki][3] = fma2_(h0, wa1.y, acc[ki][3]);
                acc[ki][0] = fma2_(h1, wb0.x, acc[ki][0]);
                acc[ki][1] = fma2_(h1, wb0.y, acc[ki][1]);
                acc[ki][2] = fma2_(h1, wb1.x, acc[ki][2]);
                acc[ki][3] = fma2_(h1, wb1.y, acc[ki][3]);
                acc[ki][0] = fma2_(h2, wc0.x, acc[ki][0]);
                acc[ki][1] = fma2_(h2, wc0.y, acc[ki][1]);
                acc[ki][2] = fma2_(h2, wc1.x, acc[ki][2]);
                acc[ki][3] = fma2_(h2, wc1.y, acc[ki][3]);
                acc[ki][0] = fma2_(h3, wd0.x, acc[ki][0]);
                acc[ki][1] = fma2_(h3, wd0.y, acc[ki][1]);
                acc[ki][2] = fma2_(h3, wd1.x, acc[ki][2]);
                acc[ki][3] = fma2_(h3, wd1.y, acc[ki][3]);
            }
        }
    }
    __syncthreads();
#pragma unroll
    for (int ki = 0; ki < 8; ki++) {
        float a0, a1, a2, a3, a4, a5, a6, a7;
        upk2(a0, a1, acc[ki][0]);
        upk2(a2, a3, acc[ki][1]);
        upk2(a4, a5, acc[ki][2]);
        upk2(a6, a7, acc[ki][3]);
        float4 v0 = make_float4(leaky(a0), leaky(a1), leaky(a2), leaky(a3));
        float4 v1 = make_float4(leaky(a4), leaky(a5), leaky(a6), leaky(a7));
        *reinterpret_cast<float4*>(hp2 + ki * HROWS + o0)     = v0;
        *reinterpret_cast<float4*>(hp2 + ki * HROWS + o0 + 4) = v1;
    }
    __syncthreads();

    // =============== layer 2 ===============
    {
        ulonglong2 bA = *reinterpret_cast<const ulonglong2*>(b1s + o0);
        ulonglong2 bB = *reinterpret_cast<const ulonglong2*>(b1s + o0 + 4);
#pragma unroll
        for (int ki = 0; ki < 8; ki++) {
            acc[ki][0] = bA.x; acc[ki][1] = bA.y;
            acc[ki][2] = bB.x; acc[ki][3] = bB.y;
        }
#pragma unroll 1
        for (int c = 0; c < 64; c += 4) {
            const float* wp = w1T + c * WSTR + o0;
            ulonglong2 wa0 = *reinterpret_cast<const ulonglong2*>(wp);
            ulonglong2 wa1 = *reinterpret_cast<const ulonglong2*>(wp + 4);
            ulonglong2 wb0 = *reinterpret_cast<const ulonglong2*>(wp + WSTR);
            ulonglong2 wb1 = *reinterpret_cast<const ulonglong2*>(wp + WSTR + 4);
            ulonglong2 wc0 = *reinterpret_cast<const ulonglong2*>(wp + 2 * WSTR);
            ulonglong2 wc1 = *reinterpret_cast<const ulonglong2*>(wp + 2 * WSTR + 4);
            ulonglong2 wd0 = *reinterpret_cast<const ulonglong2*>(wp + 3 * WSTR);
            ulonglong2 wd1 = *reinterpret_cast<const ulonglong2*>(wp + 3 * WSTR + 4);
#pragma unroll
            for (int ki = 0; ki < 8; ki++) {
                float4 hv = *reinterpret_cast<const float4*>(hp2 + ki * HROWS + c);
                ull h0 = pk2(hv.x, hv.x);
                ull h1 = pk2(hv.y, hv.y);
                ull h2 = pk2(hv.z, hv.z);
                ull h3 = pk2(hv.w, hv.w);
                acc[ki][0] = fma2_(h0, wa0.x, acc[ki][0]);
                acc[ki][1] = fma2_(h0, wa0.y, acc[ki][1]);
                acc[ki][2] = fma2_(h0, wa1.x, acc[ki][2]);
                acc[ki][3] = fma2_(h0, wa1.y, acc[ki][3]);
                acc[ki][0] = fma2_(h1, wb0.x, acc[ki][0]);
                acc[ki][1] = fma2_(h1, wb0.y, acc[ki][1]);
                acc[ki][2] = fma2_(h1, wb1.x, acc[ki][2]);
                acc[ki][3] = fma2_(h1, wb1.y, acc[ki][3]);
                acc[ki][0] = fma2_(h2, wc0.x, acc[ki][0]);
                acc[ki][1] = fma2_(h2, wc0.y, acc[ki][1]);
                acc[ki][2] = fma2_(h2, wc1.x, acc[ki][2]);
                acc[ki][3] = fma2_(h2, wc1.y, acc[ki][3]);
                acc[ki][0] = fma2_(h3, wd0.x, acc[ki][0]);
                acc[ki][1] = fma2_(h3, wd0.y, acc[ki][1]);
                acc[ki][2] = fma2_(h3, wd1.x, acc[ki][2]);
                acc[ki][3] = fma2_(h3, wd1.y, acc[ki][3]);
            }
        }
    }

    // hs is dead from here; pm aliases it — barrier before reuse
    __syncthreads();

    {
        float mx[8];
#pragma unroll
        for (int j = 0; j < 8; j++) mx[j] = -CUDART_INF_F;
#pragma unroll
        for (int ki = 0; ki < 8; ki++) {
            float a0, a1, a2, a3, a4, a5, a6, a7;
            upk2(a0, a1, acc[ki][0]);
            upk2(a2, a3, acc[ki][1]);
            upk2(a4, a5, acc[ki][2]);
            upk2(a6, a7, acc[ki][3]);
            mx[0] = fmaxf(mx[0], leaky(a0));
            mx[1] = fmaxf(mx[1], leaky(a1));
            mx[2] = fmaxf(mx[2], leaky(a2));
            mx[3] = fmaxf(mx[3], leaky(a3));
            mx[4] = fmaxf(mx[4], leaky(a4));
            mx[5] = fmaxf(mx[5], leaky(a5));
            mx[6] = fmaxf(mx[6], leaky(a6));
            mx[7] = fmaxf(mx[7], leaky(a7));
        }
        float* pmp = pm + p * 128 + (k0 >> 3) * 64 + o0;
        *reinterpret_cast<float4*>(pmp)     = make_float4(mx[0], mx[1], mx[2], mx[3]);
        *reinterpret_cast<float4*>(pmp + 4) = make_float4(mx[4], mx[5], mx[6], mx[7]);
    }
    __syncthreads();

#pragma unroll
    for (int i = 0; i < 4; i++) {
        int ii = tid + i * 128;
        int pp = ii >> 6, oo = ii & 63;
        float mm = fmaxf(pm[pp * 128 + oo], pm[pp * 128 + 64 + oo]);
        int nn = blockIdx.x * 8 + pp;
        g_ms[((size_t)dirb * NPTS + nn) * CH + oo] = mm;
    }
}

// ---------------------------------------------------------------------------
// proj: 128 threads = 128 output channels; weight row (64fl) in registers,
// 64 points staged in smem, broadcast LDS.128 activations.
// ---------------------------------------------------------------------------
#define PPROJ 64
__global__ void __launch_bounds__(128) proj_kernel(
        const float* __restrict__ t1w, const float* __restrict__ t1b,
        const float* __restrict__ t2w, const float* __restrict__ t2b,
        float* __restrict__ out) {
    __shared__ float aS[PPROJ * 64];

    const int dir = blockIdx.z;
    const int b   = blockIdx.y;
    const int j   = threadIdx.x;        // output channel
    const int dirb = dir * BATCH + b;

    const float* tw = dir ? t2w : t1w;
    const float* tb = dir ? t2b : t1b;

    float4 w[16];
#pragma unroll
    for (int t = 0; t < 16; t++)
        w[t] = reinterpret_cast<const float4*>(tw + j * 64)[t];
    const float bias = tb[j];

    const int n0 = blockIdx.x * PPROJ;
#pragma unroll
    for (int i = 0; i < PPROJ * 64 / 128 / 4; i++) {
        int f = j + i * 128;
        reinterpret_cast<float4*>(aS)[f] =
            reinterpret_cast<const float4*>(g_ms + ((size_t)dirb * NPTS + n0) * CH)[f];
    }
    __syncthreads();

#pragma unroll 2
    for (int p = 0; p < PPROJ; p++) {
        float acc = bias;
        const float4* ap = reinterpret_cast<const float4*>(aS + p * 64);
#pragma unroll
        for (int t = 0; t < 16; t++) {
            float4 a = ap[t];
            acc = fmaf(a.x, w[t].x, acc);
            acc = fmaf(a.y, w[t].y, acc);
            acc = fmaf(a.z, w[t].z, acc);
            acc = fmaf(a.w, w[t].w, acc);
        }
        out[((size_t)dirb * NPTS + n0 + p) * OUTCH + j] = acc;
    }
}

// ---------------------------------------------------------------------------
extern "C" void kernel_launch(void* const* d_in, const int* in_sizes, int n_in,
                              void* d_out, int out_size) {
    (void)in_sizes; (void)n_in; (void)out_size;
    const float* pc1   = (const float*)d_in[0];
    const float* pc2   = (const float*)d_in[1];
    const float* feat1 = (const float*)d_in[2];
    const float* feat2 = (const float*)d_in[3];
    const float* pos_w = (const float*)d_in[4];
    const float* pos_b = (const float*)d_in[5];
    const float* w0    = (const float*)d_in[6];
    const float* b0    = (const float*)d_in[7];
    const float* w1    = (const float*)d_in[8];
    const float* b1    = (const float*)d_in[9];
    const float* t1w   = (const float*)d_in[10];
    const float* t1b   = (const float*)d_in[11];
    const float* t2w   = (const float*)d_in[12];
    const float* t2b   = (const float*)d_in[13];
    float* out = (float*)d_out;

    pack_kernel<<<(2 * BATCH * NPTS + 255) / 256, 256>>>(pc1, pc2);

    // 64KB candidate tile + 16KB slot-major idx = 80KB
    const size_t ksmem = (4 * SEGSZ + NSAMPLE * KBT) * sizeof(float);
    cudaFuncSetAttribute(knn_part,
                         cudaFuncAttributeMaxDynamicSharedMemorySize, (int)ksmem);
    dim3 gk(NPTS / KBT, 2 * BATCH, SEG);
    knn_part<<<gk, KBT, ksmem>>>();

    knn_merge<<<(2 * BATCH * NPTS * 32) / 256, 256>>>();

    const size_t smem = (size_t)(64 * WSTR * 2 + 8 * HPNT + 192 + 64 * 3)
                        * sizeof(float);
    cudaFuncSetAttribute(feat_kernel,
                         cudaFuncAttributeMaxDynamicSharedMemorySize, (int)smem);
    dim3 gf(NPTS / 8, BATCH, 2);
    feat_kernel<<<gf, 128, smem>>>(feat1, feat2, pos_w, pos_b, w0, b0, w1, b1);

    dim3 gp(NPTS / PPROJ, BATCH, 2);
    proj_kernel<<<gp, 128>>>(t1w, t1b, t2w, t2b, out);
}

// round 8
// speedup vs baseline: 1.9605x; 1.0085x over previous
#include <cuda_runtime.h>
#include <math_constants.h>

#define NSAMPLE 16
#define NPTS    8192
#define BATCH   2
#define CH      64
#define OUTCH   128
#define SEG     2
#define SEGSZ   (NPTS / SEG)      // 4096
#define KBT     256               // knn block threads

typedef unsigned long long ull;
typedef unsigned int uint;
typedef unsigned short ushort;

// ---- f32x2 packed helpers (Blackwell) ----
__device__ __forceinline__ ull pk2(float a, float b) {
    ull r; asm("mov.b64 %0,{%1,%2};" : "=l"(r) : "f"(a), "f"(b)); return r;
}
__device__ __forceinline__ void upk2(float& a, float& b, ull r) {
    asm("mov.b64 {%0,%1}, %2;" : "=f"(a), "=f"(b) : "l"(r));
}
__device__ __forceinline__ ull fma2_(ull a, ull b, ull c) {
    ull d; asm("fma.rn.f32x2 %0,%1,%2,%3;" : "=l"(d) : "l"(a), "l"(b), "l"(c)); return d;
}
__device__ __forceinline__ ull mul2_(ull a, ull b) {
    ull d; asm("mul.rn.f32x2 %0,%1,%2;" : "=l"(d) : "l"(a), "l"(b)); return d;
}
__device__ __forceinline__ float leaky(float x) { return x >= 0.0f ? x : 0.1f * x; }
__device__ __forceinline__ uint umax_(uint a, uint b) { return a > b ? a : b; }

#define WSTR 68

// scratch
__device__ float4 g_pts4[2 * BATCH * NPTS];
__device__ float2 g_part[2 * BATCH * NPTS * SEG * NSAMPLE];
__device__ int    g_knn[2 * BATCH * NPTS * NSAMPLE];
__device__ float  g_ms[2 * BATCH * NPTS * CH];
__device__ __align__(16) float g_w0T[64 * WSTR];   // transposed MLP weights
__device__ __align__(16) float g_w1T[64 * WSTR];

// ---------------------------------------------------------------------------
__global__ void pack_kernel(const float* __restrict__ pc1,
                            const float* __restrict__ pc2) {
    int i = blockIdx.x * blockDim.x + threadIdx.x;
    if (i >= 2 * BATCH * NPTS) return;
    const float* src = (i < BATCH * NPTS) ? pc1 : pc2;
    int r = (i < BATCH * NPTS) ? i : (i - BATCH * NPTS);
    float x = src[r * 3 + 0], y = src[r * 3 + 1], z = src[r * 3 + 2];
    g_pts4[i] = make_float4(x, y, z, x * x + y * y + z * z);
}

// transpose MLP weights into padded global arrays (read by feat via L1)
__global__ void wprep_kernel(const float* __restrict__ w0,
                             const float* __restrict__ w1) {
    int f = blockIdx.x * blockDim.x + threadIdx.x;   // float4 index, 1024 total
    if (f >= 1024) return;
    float4 a = reinterpret_cast<const float4*>(w0)[f];
    float4 c = reinterpret_cast<const float4*>(w1)[f];
    int o = f >> 4, c0 = (f & 15) * 4;
    g_w0T[(c0 + 0) * WSTR + o] = a.x;
    g_w0T[(c0 + 1) * WSTR + o] = a.y;
    g_w0T[(c0 + 2) * WSTR + o] = a.z;
    g_w0T[(c0 + 3) * WSTR + o] = a.w;
    g_w1T[(c0 + 0) * WSTR + o] = c.x;
    g_w1T[(c0 + 1) * WSTR + o] = c.y;
    g_w1T[(c0 + 2) * WSTR + o] = c.z;
    g_w1T[(c0 + 3) * WSTR + o] = c.w;
}

// ---------------------------------------------------------------------------
// KNN pass 1. 8-candidate batches: all distances computed up-front (ILP),
// min-tree, one guard branch. Threshold-shifted compare:
//   d < wd  <=>  s := |c|^2 - 2*dot  <  wds := wd - |q|^2
// Top-16 as uint keys (dist bits, low 4 bits = slot). Indices in slot-major
// ushort smem. wd reconstructed with slot bits MASKED (NaN otherwise).
// ---------------------------------------------------------------------------
__global__ void __launch_bounds__(KBT, 3) knn_part() {
    extern __shared__ float ks[];
    float*  sx = ks;
    float*  sy = sx + SEGSZ;
    float*  sz = sy + SEGSZ;
    float*  sw = sz + SEGSZ;
    ushort* sidx = (ushort*)(sw + SEGSZ);    // [16][KBT]

    const int dirb = blockIdx.y;             // dir*2 + b
    const int dir  = dirb >> 1;
    const int b    = dirb & 1;
    const int seg  = blockIdx.z;
    const int tid  = threadIdx.x;
    const int n    = blockIdx.x * KBT + tid;

    const float4* Qb = g_pts4 + ((size_t)dir * BATCH + b) * NPTS;
    const float4* Cb = g_pts4 + ((size_t)(1 - dir) * BATCH + b) * NPTS + seg * SEGSZ;

#pragma unroll
    for (int k = 0; k < NSAMPLE; k++) sidx[k * KBT + tid] = 0;

    for (int i = tid; i < SEGSZ; i += KBT) {
        float4 c = Cb[i];
        sx[i] = c.x; sy[i] = c.y; sz[i] = c.z; sw[i] = c.w;
    }
    __syncthreads();

    const float4 q = Qb[n];
    const float sq1 = q.w;
    const ull qx2 = pk2(q.x, q.x);
    const ull qy2 = pk2(q.y, q.y);
    const ull qz2 = pk2(q.z, q.z);
    const ull m2  = pk2(-2.0f, -2.0f);

    uint bk[NSAMPLE];
#pragma unroll
    for (int k = 0; k < NSAMPLE; k++) bk[k] = 0x7F800000u | k;
    uint wdkey = 0x7F80000Fu;
    float wds  = CUDART_INF_F;               // shifted threshold wd - sq1
    const int base = seg * SEGSZ;

#pragma unroll 1
    for (int j = 0; j < SEGSZ; j += 8) {
        ulonglong2 X0 = *reinterpret_cast<const ulonglong2*>(&sx[j]);
        ulonglong2 X1 = *reinterpret_cast<const ulonglong2*>(&sx[j + 4]);
        ulonglong2 Y0 = *reinterpret_cast<const ulonglong2*>(&sy[j]);
        ulonglong2 Y1 = *reinterpret_cast<const ulonglong2*>(&sy[j + 4]);
        ulonglong2 Z0 = *reinterpret_cast<const ulonglong2*>(&sz[j]);
        ulonglong2 Z1 = *reinterpret_cast<const ulonglong2*>(&sz[j + 4]);
        ulonglong2 W0 = *reinterpret_cast<const ulonglong2*>(&sw[j]);
        ulonglong2 W1 = *reinterpret_cast<const ulonglong2*>(&sw[j + 4]);

        ull t0 = fma2_(qx2, X0.x, fma2_(qy2, Y0.x, mul2_(qz2, Z0.x)));
        ull t1 = fma2_(qx2, X0.y, fma2_(qy2, Y0.y, mul2_(qz2, Z0.y)));
        ull t2 = fma2_(qx2, X1.x, fma2_(qy2, Y1.x, mul2_(qz2, Z1.x)));
        ull t3 = fma2_(qx2, X1.y, fma2_(qy2, Y1.y, mul2_(qz2, Z1.y)));
        ull s01 = fma2_(m2, t0, W0.x);
        ull s23 = fma2_(m2, t1, W0.y);
        ull s45 = fma2_(m2, t2, W1.x);
        ull s67 = fma2_(m2, t3, W1.y);

        float s[8];
        upk2(s[0], s[1], s01);
        upk2(s[2], s[3], s23);
        upk2(s[4], s[5], s45);
        upk2(s[6], s[7], s67);

        float m4a = fminf(fminf(s[0], s[1]), fminf(s[2], s[3]));
        float m4b = fminf(fminf(s[4], s[5]), fminf(s[6], s[7]));
        float m8  = fminf(m4a, m4b);

        if (m8 < wds) {
#pragma unroll
            for (int g = 0; g < 2; g++) {
                float mg = g ? m4b : m4a;
                if (mg < wds) {
#pragma unroll
                    for (int t = 0; t < 4; t++) {
                        float sv = s[g * 4 + t];
                        if (sv < wds) {
                            float d = sv + sq1;
                            uint slot = wdkey & 15u;
                            uint nk = (__float_as_uint(fmaxf(d, 0.0f)) & 0xFFFFFFF0u) | slot;
                            sidx[slot * KBT + tid] = (ushort)(base + j + g * 4 + t);
#pragma unroll
                            for (int k = 0; k < NSAMPLE; k++)
                                bk[k] = (bk[k] == wdkey) ? nk : bk[k];
                            uint m0[8];
#pragma unroll
                            for (int k = 0; k < 8; k++) m0[k] = umax_(bk[2*k], bk[2*k+1]);
                            uint m1[4];
#pragma unroll
                            for (int k = 0; k < 4; k++) m1[k] = umax_(m0[2*k], m0[2*k+1]);
                            wdkey = umax_(umax_(m1[0], m1[1]), umax_(m1[2], m1[3]));
                            wds = __uint_as_float(wdkey & 0xFFFFFFF0u) - sq1;
                        }
                    }
                }
            }
        }
    }

    float2* outp = g_part + (((size_t)dirb * NPTS + n) * SEG + seg) * NSAMPLE;
#pragma unroll
    for (int k = 0; k < NSAMPLE; k++) {
        int idx = (int)sidx[(bk[k] & 15u) * KBT + tid];
        outp[k] = make_float2(__uint_as_float(bk[k] & 0xFFFFFFF0u),
                              __int_as_float(base + 0 * idx + idx - base));  // = idx... keep simple below
    }
}

// ---------------------------------------------------------------------------
// KNN pass 2: warp per query merges 2x16 (one entry/lane) -> exact top-16.
// NOTE: stored idx is segment-local ushort; segment base re-added via lane.
// ---------------------------------------------------------------------------
__global__ void __launch_bounds__(256) knn_merge() {
    const int gtid = blockIdx.x * 256 + threadIdx.x;
    const int q    = gtid >> 5;
    const int lane = gtid & 31;

    float2 e = g_part[(size_t)q * (SEG * NSAMPLE) + lane];
    float d = e.x; int i = __float_as_int(e.y);

    int* outp = g_knn + (size_t)q * NSAMPLE;

#pragma unroll
    for (int k = 0; k < NSAMPLE; k++) {
        float bdv = d;
        int   biv = i;
#pragma unroll
        for (int off = 16; off > 0; off >>= 1) {
            float od = __shfl_xor_sync(0xFFFFFFFFu, bdv, off);
            int   oi = __shfl_xor_sync(0xFFFFFFFFu, biv, off);
            if (od < bdv || (od == bdv && oi < biv)) { bdv = od; biv = oi; }
        }
        if (lane == 0) outp[k] = biv;
        if (d == bdv && i == biv) d = CUDART_INF_F;
    }
}

// ---------------------------------------------------------------------------
// feat: 128 threads = 8 points x 16 threads; k8 x o8 f32x2 tiles.
// Weights read from pre-transposed GLOBAL arrays (L1-resident LDG.128);
// smem holds only activations -> 37.6KB -> 4 blocks/SM (reg cap 128).
// ---------------------------------------------------------------------------
#define HROWS 68
#define HPNT  1128

__device__ __forceinline__ int hoff(int p, int k) {
    return p * HPNT + k * HROWS + ((k >> 3) << 4);
}

__global__ void __launch_bounds__(128, 4) feat_kernel(
        const float* __restrict__ feat1,
        const float* __restrict__ feat2,
        const float* __restrict__ pos_w,
        const float* __restrict__ pos_b,
        const float* __restrict__ b0,
        const float* __restrict__ b1) {
    extern __shared__ float sm[];
    float* hs    = sm;                         // 9024
    float* pm    = hs;                         // ALIAS: hs dead after layer 2
    float* posws = hs + 8 * HPNT;              // 192
    float* posbs = posws + 192;                // 64
    float* b0s   = posbs + 64;                 // 64
    float* b1s   = b0s + 64;                   // 64

    const int dir = blockIdx.z;
    const int b   = blockIdx.y;
    const int tid = threadIdx.x;
    const int dirb = dir * BATCH + b;

    if (tid < 64) {
        posbs[tid] = pos_b[tid];
        b0s[tid]   = b0[tid];
        b1s[tid]   = b1[tid];
    }
    for (int i = tid; i < 192; i += 128) posws[i] = pos_w[i];
    __syncthreads();

    const float* F1 = dir ? feat2 : feat1;
    const float* F2 = dir ? feat1 : feat2;
    const float4* QC = g_pts4 + ((size_t)dir * BATCH + b) * NPTS;
    const float4* NC = g_pts4 + ((size_t)(1 - dir) * BATCH + b) * NPTS;

    // ---- stage 1: gather + pos feat + leaky -> hs ----
    {
        const int c  = tid & 63;
        const int rh = tid >> 6;
        const float pwx = posws[c * 3 + 0];
        const float pwy = posws[c * 3 + 1];
        const float pwz = posws[c * 3 + 2];
        const float pb  = posbs[c];
        for (int it = 0; it < 64; it++) {
            int row = it * 2 + rh;
            int p = row >> 4, k = row & 15;
            int n = blockIdx.x * 8 + p;
            int id = g_knn[((size_t)dirb * NPTS + n) * NSAMPLE + k];
            float4 cc = NC[id];
            float4 qq = QC[n];
            float g   = F2[((size_t)b * NPTS + id) * CH + c];
            float p1o = F1[((size_t)b * NPTS + n) * CH + c];
            float h = g + p1o +
                fmaf(pwx, cc.x - qq.x, fmaf(pwy, cc.y - qq.y,
                fmaf(pwz, cc.z - qq.z, pb)));
            hs[hoff(p, k) + c] = leaky(h);
        }
    }
    __syncthreads();

    const int tt = tid & 15;
    const int p  = tid >> 4;
    const int o0 = (tt & 7) * 8;
    const int k0 = (tt >> 3) * 8;
    float* hp2 = hs + hoff(p, k0);

    ull acc[8][4];

    // =============== layer 1 ===============
    {
        ulonglong2 bA = *reinterpret_cast<const ulonglong2*>(b0s + o0);
        ulonglong2 bB = *reinterpret_cast<const ulonglong2*>(b0s + o0 + 4);
#pragma unroll
        for (int ki = 0; ki < 8; ki++) {
            acc[ki][0] = bA.x; acc[ki][1] = bA.y;
            acc[ki][2] = bB.x; acc[ki][3] = bB.y;
        }
#pragma unroll 1
        for (int c = 0; c < 64; c += 4) {
            const float* wp = g_w0T + c * WSTR + o0;
            ulonglong2 wa0 = *reinterpret_cast<const ulonglong2*>(wp);
            ulonglong2 wa1 = *reinterpret_cast<const ulonglong2*>(wp + 4);
            ulonglong2 wb0 = *reinterpret_cast<const ulonglong2*>(wp + WSTR);
            ulonglong2 wb1 = *reinterpret_cast<const ulonglong2*>(wp + WSTR + 4);
            ulonglong2 wc0 = *reinterpret_cast<const ulonglong2*>(wp + 2 * WSTR);
            ulonglong2 wc1 = *reinterpret_cast<const ulonglong2*>(wp + 2 * WSTR + 4);
            ulonglong2 wd0 = *reinterpret_cast<const ulonglong2*>(wp + 3 * WSTR);
            ulonglong2 wd1 = *reinterpret_cast<const ulonglong2*>(wp + 3 * WSTR + 4);
#pragma unroll
            for (int ki = 0; ki < 8; ki++) {
                float4 hv = *reinterpret_cast<const float4*>(hp2 + ki * HROWS + c);
                ull h0 = pk2(hv.x, hv.x);
                ull h1 = pk2(hv.y, hv.y);
                ull h2 = pk2(hv.z, hv.z);
                ull h3 = pk2(hv.w, hv.w);
                acc[ki][0] = fma2_(h0, wa0.x, acc[ki][0]);
                acc[ki][1] = fma2_(h0, wa0.y, acc[ki][1]);
                acc[ki][2] = fma2_(h0, wa1.x, acc[ki][2]);
                acc[ki][3] = fma2_(h0, wa1.y, acc[ki][3]);
                acc[ki][0] = fma2_(h1, wb0.x, acc[ki][0]);
                acc[ki][1] = fma2_(h1, wb0.y, acc[ki][1]);
                acc[ki][2] = fma2_(h1, wb1.x, acc[ki][2]);
                acc[ki][3] = fma2_(h1, wb1.y, acc[ki][3]);
                acc[ki][0] = fma2_(h2, wc0.x, acc[ki][0]);
                acc[ki][1] = fma2_(h2, wc0.y, acc[ki][1]);
                acc[ki][2] = fma2_(h2, wc1.x, acc[ki][2]);
                acc[ki][3] = fma2_(h2, wc1.y, acc[ki][3]);
                acc[ki][0] = fma2_(h3, wd0.x, acc[ki][0]);
                acc[ki][1] = fma2_(h3, wd0.y, acc[ki][1]);
                acc[ki][2] = fma2_(h3, wd1.x, acc[ki][2]);
                acc[ki][3] = fma2_(h3, wd1.y, acc[ki][3]);
            }
        }
    }
    __syncthreads();
#pragma unroll
    for (int ki = 0; ki < 8; ki++) {
        float a0, a1, a2, a3, a4, a5, a6, a7;
        upk2(a0, a1, acc[ki][0]);
        upk2(a2, a3, acc[ki][1]);
        upk2(a4, a5, acc[ki][2]);
        upk2(a6, a7, acc[ki][3]);
        float4 v0 = make_float4(leaky(a0), leaky(a1), leaky(a2), leaky(a3));
        float4 v1 = make_float4(leaky(a4), leaky(a5), leaky(a6), leaky(a7));
        *reinterpret_cast<float4*>(hp2 + ki * HROWS + o0)     = v0;
        *reinterpret_cast<float4*>(hp2 + ki * HROWS + o0 + 4) = v1;
    }
    __syncthreads();

    // =============== layer 2 ===============
    {
        ulonglong2 bA = *reinterpret_cast<const ulonglong2*>(b1s + o0);
        ulonglong2 bB = *reinterpret_cast<const ulonglong2*>(b1s + o0 + 4);
#pragma unroll
        for (int ki = 0; ki < 8; ki++) {
            acc[ki][0] = bA.x; acc[ki][1] = bA.y;
            acc[ki][2] = bB.x; acc[ki][3] = bB.y;
        }
#pragma unroll 1
        for (int c = 0; c < 64; c += 4) {
            const float* wp = g_w1T + c * WSTR + o0;
            ulonglong2 wa0 = *reinterpret_cast<const ulonglong2*>(wp);
            ulonglong2 wa1 = *reinterpret_cast<const ulonglong2*>(wp + 4);
            ulonglong2 wb0 = *reinterpret_cast<const ulonglong2*>(wp + WSTR);
            ulonglong2 wb1 = *reinterpret_cast<const ulonglong2*>(wp + WSTR + 4);
            ulonglong2 wc0 = *reinterpret_cast<const ulonglong2*>(wp + 2 * WSTR);
            ulonglong2 wc1 = *reinterpret_cast<const ulonglong2*>(wp + 2 * WSTR + 4);
            ulonglong2 wd0 = *reinterpret_cast<const ulonglong2*>(wp + 3 * WSTR);
            ulonglong2 wd1 = *reinterpret_cast<const ulonglong2*>(wp + 3 * WSTR + 4);
#pragma unroll
            for (int ki = 0; ki < 8; ki++) {
                float4 hv = *reinterpret_cast<const float4*>(hp2 + ki * HROWS + c);
                ull h0 = pk2(hv.x, hv.x);
                ull h1 = pk2(hv.y, hv.y);
                ull h2 = pk2(hv.z, hv.z);
                ull h3 = pk2(hv.w, hv.w);
                acc[ki][0] = fma2_(h0, wa0.x, acc[ki][0]);
                acc[ki][1] = fma2_(h0, wa0.y, acc[ki][1]);
                acc[ki][2] = fma2_(h0, wa1.x, acc[ki][2]);
                acc[ki][3] = fma2_(h0, wa1.y, acc[ki][3]);
                acc[ki][0] = fma2_(h1, wb0.x, acc[ki][0]);
                acc[ki][1] = fma2_(h1, wb0.y, acc[ki][1]);
                acc[ki][2] = fma2_(h1, wb1.x, acc[ki][2]);
                acc[ki][3] = fma2_(h1, wb1.y, acc[ki][3]);
                acc[ki][0] = fma2_(h2, wc0.x, acc[ki][0]);
                acc[ki][1] = fma2_(h2, wc0.y, acc[ki][1]);
                acc[ki][2] = fma2_(h2, wc1.x, acc[ki][2]);
                acc[ki][3] = fma2_(h2, wc1.y, acc[ki][3]);
                acc[ki][0] = fma2_(h3, wd0.x, acc[ki][0]);
                acc[ki][1] = fma2_(h3, wd0.y, acc[ki][1]);
                acc[ki][2] = fma2_(h3, wd1.x, acc[ki][2]);
                acc[ki][3] = fma2_(h3, wd1.y, acc[ki][3]);
            }
        }
    }

    // hs is dead from here; pm aliases it — barrier before reuse
    __syncthreads();

    {
        float mx[8];
#pragma unroll
        for (int j = 0; j < 8; j++) mx[j] = -CUDART_INF_F;
#pragma unroll
        for (int ki = 0; ki < 8; ki++) {
            float a0, a1, a2, a3, a4, a5, a6, a7;
            upk2(a0, a1, acc[ki][0]);
            upk2(a2, a3, acc[ki][1]);
            upk2(a4, a5, acc[ki][2]);
            upk2(a6, a7, acc[ki][3]);
            mx[0] = fmaxf(mx[0], leaky(a0));
            mx[1] = fmaxf(mx[1], leaky(a1));
            mx[2] = fmaxf(mx[2], leaky(a2));
            mx[3] = fmaxf(mx[3], leaky(a3));
            mx[4] = fmaxf(mx[4], leaky(a4));
            mx[5] = fmaxf(mx[5], leaky(a5));
            mx[6] = fmaxf(mx[6], leaky(a6));
            mx[7] = fmaxf(mx[7], leaky(a7));
        }
        float* pmp = pm + p * 128 + (k0 >> 3) * 64 + o0;
        *reinterpret_cast<float4*>(pmp)     = make_float4(mx[0], mx[1], mx[2], mx[3]);
        *reinterpret_cast<float4*>(pmp + 4) = make_float4(mx[4], mx[5], mx[6], mx[7]);
    }
    __syncthreads();

#pragma unroll
    for (int i = 0; i < 4; i++) {
        int ii = tid + i * 128;
        int pp = ii >> 6, oo = ii & 63;
        float mm = fmaxf(pm[pp * 128 + oo], pm[pp * 128 + 64 + oo]);
        int nn = blockIdx.x * 8 + pp;
        g_ms[((size_t)dirb * NPTS + nn) * CH + oo] = mm;
    }
}

// ---------------------------------------------------------------------------
// proj: 128 threads = 128 output channels; weight row (64fl) in registers,
// 64 points staged in smem, broadcast LDS.128 activations.
// ---------------------------------------------------------------------------
#define PPROJ 64
__global__ void __launch_bounds__(128) proj_kernel(
        const float* __restrict__ t1w, const float* __restrict__ t1b,
        const float* __restrict__ t2w, const float* __restrict__ t2b,
        float* __restrict__ out) {
    __shared__ float aS[PPROJ * 64];

    const int dir = blockIdx.z;
    const int b   = blockIdx.y;
    const int j   = threadIdx.x;        // output channel
    const int dirb = dir * BATCH + b;

    const float* tw = dir ? t2w : t1w;
    const float* tb = dir ? t2b : t1b;

    float4 w[16];
#pragma unroll
    for (int t = 0; t < 16; t++)
        w[t] = reinterpret_cast<const float4*>(tw + j * 64)[t];
    const float bias = tb[j];

    const int n0 = blockIdx.x * PPROJ;
#pragma unroll
    for (int i = 0; i < PPROJ * 64 / 128 / 4; i++) {
        int f = j + i * 128;
        reinterpret_cast<float4*>(aS)[f] =
            reinterpret_cast<const float4*>(g_ms + ((size_t)dirb * NPTS + n0) * CH)[f];
    }
    __syncthreads();

#pragma unroll 2
    for (int p = 0; p < PPROJ; p++) {
        float acc = bias;
        const float4* ap = reinterpret_cast<const float4*>(aS + p * 64);
#pragma unroll
        for (int t = 0; t < 16; t++) {
            float4 a = ap[t];
            acc = fmaf(a.x, w[t].x, acc);
            acc = fmaf(a.y, w[t].y, acc);
            acc = fmaf(a.z, w[t].z, acc);
            acc = fmaf(a.w, w[t].w, acc);
        }
        out[((size_t)dirb * NPTS + n0 + p) * OUTCH + j] = acc;
    }
}

// ---------------------------------------------------------------------------
extern "C" void kernel_launch(void* const* d_in, const int* in_sizes, int n_in,
                              void* d_out, int out_size) {
    (void)in_sizes; (void)n_in; (void)out_size;
    const float* pc1   = (const float*)d_in[0];
    const float* pc2   = (const float*)d_in[1];
    const float* feat1 = (const float*)d_in[2];
    const float* feat2 = (const float*)d_in[3];
    const float* pos_w = (const float*)d_in[4];
    const float* pos_b = (const float*)d_in[5];
    const float* w0    = (const float*)d_in[6];
    const float* b0    = (const float*)d_in[7];
    const float* w1    = (const float*)d_in[8];
    const float* b1    = (const float*)d_in[9];
    const float* t1w   = (const float*)d_in[10];
    const float* t1b   = (const float*)d_in[11];
    const float* t2w   = (const float*)d_in[12];
    const float* t2b   = (const float*)d_in[13];
    float* out = (float*)d_out;

    pack_kernel<<<(2 * BATCH * NPTS + 255) / 256, 256>>>(pc1, pc2);
    wprep_kernel<<<4, 256>>>(w0, w1);

    // 64KB candidate tile + 8KB ushort slot-major idx = 72KB
    const size_t ksmem = 4 * SEGSZ * sizeof(float) + NSAMPLE * KBT * sizeof(ushort);
    cudaFuncSetAttribute(knn_part,
                         cudaFuncAttributeMaxDynamicSharedMemorySize, (int)ksmem);
    dim3 gk(NPTS / KBT, 2 * BATCH, SEG);
    knn_part<<<gk, KBT, ksmem>>>();

    knn_merge<<<(2 * BATCH * NPTS * 32) / 256, 256>>>();

    const size_t smem = (size_t)(8 * HPNT + 192 + 64 * 3) * sizeof(float);
    cudaFuncSetAttribute(feat_kernel,
                         cudaFuncAttributeMaxDynamicSharedMemorySize, (int)smem);
    dim3 gf(NPTS / 8, BATCH, 2);
    feat_kernel<<<gf, 128, smem>>>(feat1, feat2, pos_w, pos_b, b0, b1);

    dim3 gp(NPTS / PPROJ, BATCH, 2);
    proj_kernel<<<gp, 128>>>(t1w, t1b, t2w, t2b, out);
}

// round 11
// speedup vs baseline: 2.1156x; 1.0791x over previous
#include <cuda_runtime.h>
#include <math_constants.h>
#include <cstdint>

#define NSAMPLE 16
#define NPTS    8192
#define BATCH   2
#define CH      64
#define OUTCH   128
#define SEGSZ   4096              // candidates per pass
#define KBT     256               // knn block threads

typedef unsigned long long ull;
typedef unsigned int uint;
typedef unsigned short ushort;

// ---- f32x2 packed helpers (Blackwell) ----
__device__ __forceinline__ ull pk2(float a, float b) {
    ull r; asm("mov.b64 %0,{%1,%2};" : "=l"(r) : "f"(a), "f"(b)); return r;
}
__device__ __forceinline__ void upk2(float& a, float& b, ull r) {
    asm("mov.b64 {%0,%1}, %2;" : "=f"(a), "=f"(b) : "l"(r));
}
__device__ __forceinline__ ull fma2_(ull a, ull b, ull c) {
    ull d; asm("fma.rn.f32x2 %0,%1,%2,%3;" : "=l"(d) : "l"(a), "l"(b), "l"(c)); return d;
}
__device__ __forceinline__ ull mul2_(ull a, ull b) {
    ull d; asm("mul.rn.f32x2 %0,%1,%2;" : "=l"(d) : "l"(a), "l"(b)); return d;
}
__device__ __forceinline__ float leaky(float x) { return x >= 0.0f ? x : 0.1f * x; }
__device__ __forceinline__ uint umax_(uint a, uint b) { return a > b ? a : b; }

#define WSTR 68

// scratch
__device__ float4 g_pts4[2 * BATCH * NPTS];
__device__ uint   g_skey[2 * BATCH * NPTS * NSAMPLE];   // pass-1 checkpoint keys
__device__ ushort g_sidg[2 * BATCH * NPTS * NSAMPLE];   // pass-1 checkpoint idx
__device__ int    g_knn[2 * BATCH * NPTS * NSAMPLE];
__device__ float  g_ms[2 * BATCH * NPTS * CH];
__device__ __align__(16) float g_w0T[64 * WSTR];        // transposed MLP weights
__device__ __align__(16) float g_w1T[64 * WSTR];

// ---------------------------------------------------------------------------
__global__ void pack_kernel(const float* __restrict__ pc1,
                            const float* __restrict__ pc2) {
    int i = blockIdx.x * blockDim.x + threadIdx.x;
    if (i >= 2 * BATCH * NPTS) return;
    const float* src = (i < BATCH * NPTS) ? pc1 : pc2;
    int r = (i < BATCH * NPTS) ? i : (i - BATCH * NPTS);
    float x = src[r * 3 + 0], y = src[r * 3 + 1], z = src[r * 3 + 2];
    g_pts4[i] = make_float4(x, y, z, x * x + y * y + z * z);
}

// transpose MLP weights into padded global arrays (read by feat via L1)
__global__ void wprep_kernel(const float* __restrict__ w0,
                             const float* __restrict__ w1) {
    int f = blockIdx.x * blockDim.x + threadIdx.x;   // float4 index, 1024 total
    if (f >= 1024) return;
    float4 a = reinterpret_cast<const float4*>(w0)[f];
    float4 c = reinterpret_cast<const float4*>(w1)[f];
    int o = f >> 4, c0 = (f & 15) * 4;
    g_w0T[(c0 + 0) * WSTR + o] = a.x;
    g_w0T[(c0 + 1) * WSTR + o] = a.y;
    g_w0T[(c0 + 2) * WSTR + o] = a.z;
    g_w0T[(c0 + 3) * WSTR + o] = a.w;
    g_w1T[(c0 + 0) * WSTR + o] = c.x;
    g_w1T[(c0 + 1) * WSTR + o] = c.y;
    g_w1T[(c0 + 2) * WSTR + o] = c.z;
    g_w1T[(c0 + 3) * WSTR + o] = c.w;
}

// ---------------------------------------------------------------------------
// KNN, chained two-pass. Pass 0 scans candidates [0,4096) from a cold top-16
// and checkpoints (keys, idx) to global. Pass 1 RESUMES that state over
// [4096,8192) — threshold already tight, so maintenance events are rare —
// and writes g_knn directly (no merge kernel).
// Body identical to R8: uint keys (dist bits | slot, dist clamped >= 0),
// slot-major ushort index smem, 8-candidate batches, shifted threshold.
// ---------------------------------------------------------------------------
__global__ void __launch_bounds__(KBT, 3) knn_part(int pass) {
    extern __shared__ float ks[];
    float*  sx = ks;
    float*  sy = sx + SEGSZ;
    float*  sz = sy + SEGSZ;
    float*  sw = sz + SEGSZ;
    ushort* sidx = (ushort*)(sw + SEGSZ);    // [16][KBT], holds GLOBAL idx (<8192)

    const int dirb = blockIdx.y;             // dir*2 + b
    const int dir  = dirb >> 1;
    const int b    = dirb & 1;
    const int tid  = threadIdx.x;
    const int n    = blockIdx.x * KBT + tid;
    const int base = pass * SEGSZ;
    const size_t q = (size_t)dirb * NPTS + n;

    const float4* Qb = g_pts4 + ((size_t)dir * BATCH + b) * NPTS;
    const float4* Cb = g_pts4 + ((size_t)(1 - dir) * BATCH + b) * NPTS + base;

    uint bk[NSAMPLE];
    uint wdkey;

    if (pass == 0) {
#pragma unroll
        for (int k = 0; k < NSAMPLE; k++) {
            bk[k] = 0x7F800000u | k;
            sidx[k * KBT + tid] = 0;
        }
        wdkey = 0x7F80000Fu;
    } else {
        // resume checkpointed state
#pragma unroll
        for (int k = 0; k < NSAMPLE; k++) {
            bk[k] = g_skey[q * NSAMPLE + k];
            sidx[(bk[k] & 15u) * KBT + tid] = g_sidg[q * NSAMPLE + k];
        }
        uint m0[8];
#pragma unroll
        for (int k = 0; k < 8; k++) m0[k] = umax_(bk[2*k], bk[2*k+1]);
        uint m1[4];
#pragma unroll
        for (int k = 0; k < 4; k++) m1[k] = umax_(m0[2*k], m0[2*k+1]);
        wdkey = umax_(umax_(m1[0], m1[1]), umax_(m1[2], m1[3]));
    }

    for (int i = tid; i < SEGSZ; i += KBT) {
        float4 c = Cb[i];
        sx[i] = c.x; sy[i] = c.y; sz[i] = c.z; sw[i] = c.w;
    }
    __syncthreads();

    const float4 qv = Qb[n];
    const float sq1 = qv.w;
    const ull qx2 = pk2(qv.x, qv.x);
    const ull qy2 = pk2(qv.y, qv.y);
    const ull qz2 = pk2(qv.z, qv.z);
    const ull m2  = pk2(-2.0f, -2.0f);

    float wds = __uint_as_float(wdkey & 0xFFFFFFF0u) - sq1;

#pragma unroll 1
    for (int j = 0; j < SEGSZ; j += 8) {
        ulonglong2 X0 = *reinterpret_cast<const ulonglong2*>(&sx[j]);
        ulonglong2 X1 = *reinterpret_cast<const ulonglong2*>(&sx[j + 4]);
        ulonglong2 Y0 = *reinterpret_cast<const ulonglong2*>(&sy[j]);
        ulonglong2 Y1 = *reinterpret_cast<const ulonglong2*>(&sy[j + 4]);
        ulonglong2 Z0 = *reinterpret_cast<const ulonglong2*>(&sz[j]);
        ulonglong2 Z1 = *reinterpret_cast<const ulonglong2*>(&sz[j + 4]);
        ulonglong2 W0 = *reinterpret_cast<const ulonglong2*>(&sw[j]);
        ulonglong2 W1 = *reinterpret_cast<const ulonglong2*>(&sw[j + 4]);

        ull t0 = fma2_(qx2, X0.x, fma2_(qy2, Y0.x, mul2_(qz2, Z0.x)));
        ull t1 = fma2_(qx2, X0.y, fma2_(qy2, Y0.y, mul2_(qz2, Z0.y)));
        ull t2 = fma2_(qx2, X1.x, fma2_(qy2, Y1.x, mul2_(qz2, Z1.x)));
        ull t3 = fma2_(qx2, X1.y, fma2_(qy2, Y1.y, mul2_(qz2, Z1.y)));
        ull s01 = fma2_(m2, t0, W0.x);
        ull s23 = fma2_(m2, t1, W0.y);
        ull s45 = fma2_(m2, t2, W1.x);
        ull s67 = fma2_(m2, t3, W1.y);

        float s[8];
        upk2(s[0], s[1], s01);
        upk2(s[2], s[3], s23);
        upk2(s[4], s[5], s45);
        upk2(s[6], s[7], s67);

        float m4a = fminf(fminf(s[0], s[1]), fminf(s[2], s[3]));
        float m4b = fminf(fminf(s[4], s[5]), fminf(s[6], s[7]));
        float m8  = fminf(m4a, m4b);

        if (m8 < wds) {
#pragma unroll
            for (int g = 0; g < 2; g++) {
                float mg = g ? m4b : m4a;
                if (mg < wds) {
#pragma unroll
                    for (int t = 0; t < 4; t++) {
                        float sv = s[g * 4 + t];
                        if (sv < wds) {
                            float d = sv + sq1;
                            uint slot = wdkey & 15u;
                            uint nk = (__float_as_uint(fmaxf(d, 0.0f)) & 0xFFFFFFF0u) | slot;
                            sidx[slot * KBT + tid] = (ushort)(base + j + g * 4 + t);
#pragma unroll
                            for (int k = 0; k < NSAMPLE; k++)
                                bk[k] = (bk[k] == wdkey) ? nk : bk[k];
                            uint m0[8];
#pragma unroll
                            for (int k = 0; k < 8; k++) m0[k] = umax_(bk[2*k], bk[2*k+1]);
                            uint m1[4];
#pragma unroll
                            for (int k = 0; k < 4; k++) m1[k] = umax_(m0[2*k], m0[2*k+1]);
                            wdkey = umax_(umax_(m1[0], m1[1]), umax_(m1[2], m1[3]));
                            wds = __uint_as_float(wdkey & 0xFFFFFFF0u) - sq1;
                        }
                    }
                }
            }
        }
    }

    if (pass == 0) {
        // checkpoint
#pragma unroll
        for (int k = 0; k < NSAMPLE; k++) {
            g_skey[q * NSAMPLE + k] = bk[k];
            g_sidg[q * NSAMPLE + k] = sidx[(bk[k] & 15u) * KBT + tid];
        }
    } else {
        // final: indices in sidx are global already
        int* outp = g_knn + q * NSAMPLE;
#pragma unroll
        for (int k = 0; k < NSAMPLE; k++)
            outp[k] = (int)sidx[(bk[k] & 15u) * KBT + tid];
    }
}

// ---------------------------------------------------------------------------
// feat (R8 known-good): 128 threads = 8 points x 16 threads; k8 x o8 f32x2
// tiles; weights from pre-transposed global (L1); pm aliases hs.
// ---------------------------------------------------------------------------
#define HROWS 68
#define HPNT  1128

__device__ __forceinline__ int hoff(int p, int k) {
    return p * HPNT + k * HROWS + ((k >> 3) << 4);
}

__global__ void __launch_bounds__(128, 4) feat_kernel(
        const float* __restrict__ feat1,
        const float* __restrict__ feat2,
        const float* __restrict__ pos_w,
        const float* __restrict__ pos_b,
        const float* __restrict__ b0,
        const float* __restrict__ b1) {
    extern __shared__ float sm[];
    float* hs    = sm;                         // 9024
    float* pm    = hs;                         // ALIAS: hs dead after layer 2
    float* posws = hs + 8 * HPNT;              // 192
    float* posbs = posws + 192;                // 64
    float* b0s   = posbs + 64;                 // 64
    float* b1s   = b0s + 64;                   // 64

    const int dir = blockIdx.z;
    const int b   = blockIdx.y;
    const int tid = threadIdx.x;
    const int dirb = dir * BATCH + b;

    if (tid < 64) {
        posbs[tid] = pos_b[tid];
        b0s[tid]   = b0[tid];
        b1s[tid]   = b1[tid];
    }
    for (int i = tid; i < 192; i += 128) posws[i] = pos_w[i];
    __syncthreads();

    const float* F1 = dir ? feat2 : feat1;
    const float* F2 = dir ? feat1 : feat2;
    const float4* QC = g_pts4 + ((size_t)dir * BATCH + b) * NPTS;
    const float4* NC = g_pts4 + ((size_t)(1 - dir) * BATCH + b) * NPTS;

    // ---- stage 1: gather + pos feat + leaky -> hs ----
    {
        const int c  = tid & 63;
        const int rh = tid >> 6;
        const float pwx = posws[c * 3 + 0];
        const float pwy = posws[c * 3 + 1];
        const float pwz = posws[c * 3 + 2];
        const float pb  = posbs[c];
        for (int it = 0; it < 64; it++) {
            int row = it * 2 + rh;
            int p = row >> 4, k = row & 15;
            int n = blockIdx.x * 8 + p;
            int id = g_knn[((size_t)dirb * NPTS + n) * NSAMPLE + k];
            float4 cc = NC[id];
            float4 qq = QC[n];
            float g   = F2[((size_t)b * NPTS + id) * CH + c];
            float p1o = F1[((size_t)b * NPTS + n) * CH + c];
            float h = g + p1o +
                fmaf(pwx, cc.x - qq.x, fmaf(pwy, cc.y - qq.y,
                fmaf(pwz, cc.z - qq.z, pb)));
            hs[hoff(p, k) + c] = leaky(h);
        }
    }
    __syncthreads();

    const int tt = tid & 15;
    const int p  = tid >> 4;
    const int o0 = (tt & 7) * 8;
    const int k0 = (tt >> 3) * 8;
    float* hp2 = hs + hoff(p, k0);

    ull acc[8][4];

    // =============== layer 1 ===============
    {
        ulonglong2 bA = *reinterpret_cast<const ulonglong2*>(b0s + o0);
        ulonglong2 bB = *reinterpret_cast<const ulonglong2*>(b0s + o0 + 4);
#pragma unroll
        for (int ki = 0; ki < 8; ki++) {
            acc[ki][0] = bA.x; acc[ki][1] = bA.y;
            acc[ki][2] = bB.x; acc[ki][3] = bB.y;
        }
#pragma unroll 1
        for (int c = 0; c < 64; c += 4) {
            const float* wp = g_w0T + c * WSTR + o0;
            ulonglong2 wa0 = *reinterpret_cast<const ulonglong2*>(wp);
            ulonglong2 wa1 = *reinterpret_cast<const ulonglong2*>(wp + 4);
            ulonglong2 wb0 = *reinterpret_cast<const ulonglong2*>(wp + WSTR);
            ulonglong2 wb1 = *reinterpret_cast<const ulonglong2*>(wp + WSTR + 4);
            ulonglong2 wc0 = *reinterpret_cast<const ulonglong2*>(wp + 2 * WSTR);
            ulonglong2 wc1 = *reinterpret_cast<const ulonglong2*>(wp + 2 * WSTR + 4);
            ulonglong2 wd0 = *reinterpret_cast<const ulonglong2*>(wp + 3 * WSTR);
            ulonglong2 wd1 = *reinterpret_cast<const ulonglong2*>(wp + 3 * WSTR + 4);
#pragma unroll
            for (int ki = 0; ki < 8; ki++) {
                float4 hv = *reinterpret_cast<const float4*>(hp2 + ki * HROWS + c);
                ull h0 = pk2(hv.x, hv.x);
                ull h1 = pk2(hv.y, hv.y);
                ull h2 = pk2(hv.z, hv.z);
                ull h3 = pk2(hv.w, hv.w);
                acc[ki][0] = fma2_(h0, wa0.x, acc[ki][0]);
                acc[ki][1] = fma2_(h0, wa0.y, acc[ki][1]);
                acc[ki][2] = fma2_(h0, wa1.x, acc[ki][2]);
                acc[ki][3] = fma2_(h0, wa1.y, acc[ki][3]);
                acc[ki][0] = fma2_(h1, wb0.x, acc[ki][0]);
                acc[ki][1] = fma2_(h1, wb0.y, acc[ki][1]);
                acc[ki][2] = fma2_(h1, wb1.x, acc[ki][2]);
                acc[ki][3] = fma2_(h1, wb1.y, acc[ki][3]);
                acc[ki][0] = fma2_(h2, wc0.x, acc[ki][0]);
                acc[ki][1] = fma2_(h2, wc0.y, acc[ki][1]);
                acc[ki][2] = fma2_(h2, wc1.x, acc[ki][2]);
                acc[ki][3] = fma2_(h2, wc1.y, acc[ki][3]);
                acc[ki][0] = fma2_(h3, wd0.x, acc[ki][0]);
                acc[ki][1] = fma2_(h3, wd0.y, acc[ki][1]);
                acc[ki][2] = fma2_(h3, wd1.x, acc[ki][2]);
                acc[ki][3] = fma2_(h3, wd1.y, acc[ki][3]);
            }
        }
    }
    __syncthreads();
#pragma unroll
    for (int ki = 0; ki < 8; ki++) {
        float a0, a1, a2, a3, a4, a5, a6, a7;
        upk2(a0, a1, acc[ki][0]);
        upk2(a2, a3, acc[ki][1]);
        upk2(a4, a5, acc[ki][2]);
        upk2(a6, a7, acc[ki][3]);
        float4 v0 = make_float4(leaky(a0), leaky(a1), leaky(a2), leaky(a3));
        float4 v1 = make_float4(leaky(a4), leaky(a5), leaky(a6), leaky(a7));
        *reinterpret_cast<float4*>(hp2 + ki * HROWS + o0)     = v0;
        *reinterpret_cast<float4*>(hp2 + ki * HROWS + o0 + 4) = v1;
    }
    __syncthreads();

    // =============== layer 2 ===============
    {
        ulonglong2 bA = *reinterpret_cast<const ulonglong2*>(b1s + o0);
        ulonglong2 bB = *reinterpret_cast<const ulonglong2*>(b1s + o0 + 4);
#pragma unroll
        for (int ki = 0; ki < 8; ki++) {
            acc[ki][0] = bA.x; acc[ki][1] = bA.y;
            acc[ki][2] = bB.x; acc[ki][3] = bB.y;
        }
#pragma unroll 1
        for (int c = 0; c < 64; c += 4) {
            const float* wp = g_w1T + c * WSTR + o0;
            ulonglong2 wa0 = *reinterpret_cast<const ulonglong2*>(wp);
            ulonglong2 wa1 = *reinterpret_cast<const ulonglong2*>(wp + 4);
            ulonglong2 wb0 = *reinterpret_cast<const ulonglong2*>(wp + WSTR);
            ulonglong2 wb1 = *reinterpret_cast<const ulonglong2*>(wp + WSTR + 4);
            ulonglong2 wc0 = *reinterpret_cast<const ulonglong2*>(wp + 2 * WSTR);
            ulonglong2 wc1 = *reinterpret_cast<const ulonglong2*>(wp + 2 * WSTR + 4);
            ulonglong2 wd0 = *reinterpret_cast<const ulonglong2*>(wp + 3 * WSTR);
            ulonglong2 wd1 = *reinterpret_cast<const ulonglong2*>(wp + 3 * WSTR + 4);
#pragma unroll
            for (int ki = 0; ki < 8; ki++) {
                float4 hv = *reinterpret_cast<const float4*>(hp2 + ki * HROWS + c);
                ull h0 = pk2(hv.x, hv.x);
                ull h1 = pk2(hv.y, hv.y);
                ull h2 = pk2(hv.z, hv.z);
                ull h3 = pk2(hv.w, hv.w);
                acc[ki][0] = fma2_(h0, wa0.x, acc[ki][0]);
                acc[ki][1] = fma2_(h0, wa0.y, acc[ki][1]);
                acc[ki][2] = fma2_(h0, wa1.x, acc[ki][2]);
                acc[ki][3] = fma2_(h0, wa1.y, acc[ki][3]);
                acc[ki][0] = fma2_(h1, wb0.x, acc[ki][0]);
                acc[ki][1] = fma2_(h1, wb0.y, acc[ki][1]);
                acc[ki][2] = fma2_(h1, wb1.x, acc[ki][2]);
                acc[ki][3] = fma2_(h1, wb1.y, acc[ki][3]);
                acc[ki][0] = fma2_(h2, wc0.x, acc[ki][0]);
                acc[ki][1] = fma2_(h2, wc0.y, acc[ki][1]);
                acc[ki][2] = fma2_(h2, wc1.x, acc[ki][2]);
                acc[ki][3] = fma2_(h2, wc1.y, acc[ki][3]);
                acc[ki][0] = fma2_(h3, wd0.x, acc[ki][0]);
                acc[ki][1] = fma2_(h3, wd0.y, acc[ki][1]);
                acc[ki][2] = fma2_(h3, wd1.x, acc[ki][2]);
                acc[ki][3] = fma2_(h3, wd1.y, acc[ki][3]);
            }
        }
    }

    // hs is dead from here; pm aliases it — barrier before reuse
    __syncthreads();

    {
        float mx[8];
#pragma unroll
        for (int j = 0; j < 8; j++) mx[j] = -CUDART_INF_F;
#pragma unroll
        for (int ki = 0; ki < 8; ki++) {
            float a0, a1, a2, a3, a4, a5, a6, a7;
            upk2(a0, a1, acc[ki][0]);
            upk2(a2, a3, acc[ki][1]);
            upk2(a4, a5, acc[ki][2]);
            upk2(a6, a7, acc[ki][3]);
            mx[0] = fmaxf(mx[0], leaky(a0));
            mx[1] = fmaxf(mx[1], leaky(a1));
            mx[2] = fmaxf(mx[2], leaky(a2));
            mx[3] = fmaxf(mx[3], leaky(a3));
            mx[4] = fmaxf(mx[4], leaky(a4));
            mx[5] = fmaxf(mx[5], leaky(a5));
            mx[6] = fmaxf(mx[6], leaky(a6));
            mx[7] = fmaxf(mx[7], leaky(a7));
        }
        float* pmp = pm + p * 128 + (k0 >> 3) * 64 + o0;
        *reinterpret_cast<float4*>(pmp)     = make_float4(mx[0], mx[1], mx[2], mx[3]);
        *reinterpret_cast<float4*>(pmp + 4) = make_float4(mx[4], mx[5], mx[6], mx[7]);
    }
    __syncthreads();

#pragma unroll
    for (int i = 0; i < 4; i++) {
        int ii = tid + i * 128;
        int pp = ii >> 6, oo = ii & 63;
        float mm = fmaxf(pm[pp * 128 + oo], pm[pp * 128 + 64 + oo]);
        int nn = blockIdx.x * 8 + pp;
        g_ms[((size_t)dirb * NPTS + nn) * CH + oo] = mm;
    }
}

// ---------------------------------------------------------------------------
// proj: 128 threads = 128 output channels; weight row in registers,
// 64 points staged in smem, broadcast LDS.128 activations.
// ---------------------------------------------------------------------------
#define PPROJ 64
__global__ void __launch_bounds__(128) proj_kernel(
        const float* __restrict__ t1w, const float* __restrict__ t1b,
        const float* __restrict__ t2w, const float* __restrict__ t2b,
        float* __restrict__ out) {
    __shared__ float aS[PPROJ * 64];

    const int dir = blockIdx.z;
    const int b   = blockIdx.y;
    const int j   = threadIdx.x;
    const int dirb = dir * BATCH + b;

    const float* tw = dir ? t2w : t1w;
    const float* tb = dir ? t2b : t1b;

    float4 w[16];
#pragma unroll
    for (int t = 0; t < 16; t++)
        w[t] = reinterpret_cast<const float4*>(tw + j * 64)[t];
    const float bias = tb[j];

    const int n0 = blockIdx.x * PPROJ;
#pragma unroll
    for (int i = 0; i < PPROJ * 64 / 128 / 4; i++) {
        int f = j + i * 128;
        reinterpret_cast<float4*>(aS)[f] =
            reinterpret_cast<const float4*>(g_ms + ((size_t)dirb * NPTS + n0) * CH)[f];
    }
    __syncthreads();

#pragma unroll 2
    for (int p = 0; p < PPROJ; p++) {
        float acc = bias;
        const float4* ap = reinterpret_cast<const float4*>(aS + p * 64);
#pragma unroll
        for (int t = 0; t < 16; t++) {
            float4 a = ap[t];
            acc = fmaf(a.x, w[t].x, acc);
            acc = fmaf(a.y, w[t].y, acc);
            acc = fmaf(a.z, w[t].z, acc);
            acc = fmaf(a.w, w[t].w, acc);
        }
        out[((size_t)dirb * NPTS + n0 + p) * OUTCH + j] = acc;
    }
}

// ---------------------------------------------------------------------------
extern "C" void kernel_launch(void* const* d_in, const int* in_sizes, int n_in,
                              void* d_out, int out_size) {
    (void)in_sizes; (void)n_in; (void)out_size;
    const float* pc1   = (const float*)d_in[0];
    const float* pc2   = (const float*)d_in[1];
    const float* feat1 = (const float*)d_in[2];
    const float* feat2 = (const float*)d_in[3];
    const float* pos_w = (const float*)d_in[4];
    const float* pos_b = (const float*)d_in[5];
    const float* w0    = (const float*)d_in[6];
    const float* b0    = (const float*)d_in[7];
    const float* w1    = (const float*)d_in[8];
    const float* b1    = (const float*)d_in[9];
    const float* t1w   = (const float*)d_in[10];
    const float* t1b   = (const float*)d_in[11];
    const float* t2w   = (const float*)d_in[12];
    const float* t2b   = (const float*)d_in[13];
    float* out = (float*)d_out;

    pack_kernel<<<(2 * BATCH * NPTS + 255) / 256, 256>>>(pc1, pc2);
    wprep_kernel<<<4, 256>>>(w0, w1);

    // 64KB candidate tile + 8KB ushort slot-major idx = 72KB
    const size_t ksmem = 4 * SEGSZ * sizeof(float) + NSAMPLE * KBT * sizeof(ushort);
    cudaFuncSetAttribute(knn_part,
                         cudaFuncAttributeMaxDynamicSharedMemorySize, (int)ksmem);
    dim3 gk(NPTS / KBT, 2 * BATCH);
    knn_part<<<gk, KBT, ksmem>>>(0);   // pass 1: candidates [0, 4096)
    knn_part<<<gk, KBT, ksmem>>>(1);   // pass 2: resume over [4096, 8192)

    const size_t smem = (size_t)(8 * HPNT + 192 + 64 * 3) * sizeof(float);
    cudaFuncSetAttribute(feat_kernel,
                         cudaFuncAttributeMaxDynamicSharedMemorySize, (int)smem);
    dim3 gf(NPTS / 8, BATCH, 2);
    feat_kernel<<<gf, 128, smem>>>(feat1, feat2, pos_w, pos_b, b0, b1);

    dim3 gp(NPTS / PPROJ, BATCH, 2);
    proj_kernel<<<gp, 128>>>(t1w, t1b, t2w, t2b, out);
}